// round 13
// baseline (speedup 1.0000x reference)
#include <cuda_runtime.h>
#include <cuda_bf16.h>
#include <math.h>
#include <stdint.h>

// Problem constants
constexpr int Bn = 4, Sn = 1024, Tn = 1024, Dn = 1024, Fn = 4096;
constexpr int Mrows = Bn * Sn;           // 4096
constexpr float SCALE = 0.125f;          // 1/sqrt(64)

// ---------------- scratch (static device globals: allocation-free) -------------
__device__ __align__(256) float g_h  [Mrows * Dn];             // fp32 hidden

__device__ __align__(256) __nv_bfloat16 g_qkvh[Mrows * 3 * Dn];
__device__ __align__(256) __nv_bfloat16 g_qkvl[Mrows * 3 * Dn];
__device__ __align__(256) __nv_bfloat16 g_qh  [Mrows * Dn];
__device__ __align__(256) __nv_bfloat16 g_ql  [Mrows * Dn];
__device__ __align__(256) __nv_bfloat16 g_kvh [Mrows * 2 * Dn];
__device__ __align__(256) __nv_bfloat16 g_kvl [Mrows * 2 * Dn];
__device__ __align__(256) __nv_bfloat16 g_vth [64 * 64 * 1024];
__device__ __align__(256) __nv_bfloat16 g_vtl [64 * 64 * 1024];

__device__ __align__(256) __nv_bfloat16 g_lnh [Mrows * Dn];
__device__ __align__(256) __nv_bfloat16 g_lnl [Mrows * Dn];
__device__ __align__(256) __nv_bfloat16 g_ctxh[Mrows * Dn];
__device__ __align__(256) __nv_bfloat16 g_ctxl[Mrows * Dn];
__device__ __align__(256) __nv_bfloat16 g_ench[Mrows * Dn];
__device__ __align__(256) __nv_bfloat16 g_encl[Mrows * Dn];
__device__ __align__(256) __nv_bfloat16 g_ffnh[(size_t)Mrows * Fn];
__device__ __align__(256) __nv_bfloat16 g_ffnl[(size_t)Mrows * Fn];
__device__ __align__(256) __nv_bfloat16 g_wth[16 * 1024 * 1024];
__device__ __align__(256) __nv_bfloat16 g_wtl[16 * 1024 * 1024];
constexpr size_t OW_QKV = 0;
constexpr size_t OW_AO  = OW_QKV + 3u*1024*1024;
constexpr size_t OW_Q   = OW_AO  + 1u*1024*1024;
constexpr size_t OW_KV  = OW_Q   + 1u*1024*1024;
constexpr size_t OW_CO  = OW_KV  + 2u*1024*1024;
constexpr size_t OW_FI  = OW_CO  + 1u*1024*1024;
constexpr size_t OW_FO  = OW_FI  + 4u*1024*1024;

// ================= helpers ======================================================
__device__ __forceinline__ uint32_t s2u(const void* p) {
    uint32_t a;
    asm("{ .reg .u64 t; cvta.to.shared.u64 t, %1; cvt.u32.u64 %0, t; }" : "=r"(a) : "l"(p));
    return a;
}
__device__ __forceinline__ void ldsm4(uint32_t& r0, uint32_t& r1, uint32_t& r2, uint32_t& r3,
                                      uint32_t a) {
    asm volatile("ldmatrix.sync.aligned.m8n8.x4.shared.b16 {%0,%1,%2,%3}, [%4];"
        : "=r"(r0), "=r"(r1), "=r"(r2), "=r"(r3) : "r"(a));
}
__device__ __forceinline__ void mma16816(float* c, const uint32_t* a, uint32_t b0, uint32_t b1) {
    asm volatile(
        "mma.sync.aligned.m16n8k16.row.col.f32.bf16.bf16.f32 "
        "{%0,%1,%2,%3}, {%4,%5,%6,%7}, {%8,%9}, {%0,%1,%2,%3};"
        : "+f"(c[0]), "+f"(c[1]), "+f"(c[2]), "+f"(c[3])
        : "r"(a[0]), "r"(a[1]), "r"(a[2]), "r"(a[3]), "r"(b0), "r"(b1));
}
__device__ __forceinline__ void cpa16(uint32_t dst, const void* src) {
    asm volatile("cp.async.ca.shared.global [%0], [%1], 16;" :: "r"(dst), "l"(src));
}
__device__ __forceinline__ void cpa4(uint32_t dst, const void* src) {
    asm volatile("cp.async.ca.shared.global [%0], [%1], 4;" :: "r"(dst), "l"(src));
}
__device__ __forceinline__ void split2(float x, __nv_bfloat16& h, __nv_bfloat16& l) {
    h = __float2bfloat16(x);
    l = __float2bfloat16(x - __bfloat162float(h));
}
__device__ __forceinline__ uint32_t packbf(__nv_bfloat16 a, __nv_bfloat16 b) {
    __nv_bfloat162 t(a, b);
    return *(uint32_t*)&t;
}

// ================= tensor-core split-bf16 GEMM (mma.sync HMMA) ==================
template<int BN>
__global__ __launch_bounds__(256, 2)
void tgemm(const __nv_bfloat16* __restrict__ Ah_, const __nv_bfloat16* __restrict__ Al_,
           int lda, size_t sAb, size_t sAh,
           const __nv_bfloat16* __restrict__ Bh_, const __nv_bfloat16* __restrict__ Bl_,
           int ldb, size_t sBb, size_t sBh,
           const float* __restrict__ bias, const float* __restrict__ res,
           float* __restrict__ Cf, __nv_bfloat16* __restrict__ Ch, __nv_bfloat16* __restrict__ Cl,
           int ldc, size_t sCb, size_t sCh,
           int K, int gelu)
{
    constexpr int STAGE = 16384 + BN * 128;
    constexpr int LP    = (128 + BN) * 8 / 256;
    constexpr int NTC   = BN / 16;
    constexpr int NJ    = BN / 32;

    extern __shared__ __align__(1024) char smraw[];
    const uint32_t sbase = s2u(smraw);
    const int tid = threadIdx.x, lane = tid & 31, wid = tid >> 5;
    const int z = blockIdx.z, zb = z >> 4, zh = z & 15;
    const int m0 = blockIdx.y * 128, n0 = blockIdx.x * BN;
    const int wm = wid & 3, wn = wid >> 2;

    const __nv_bfloat16* Ahp = Ah_ + zb * sAb + zh * sAh + (size_t)m0 * lda;
    const __nv_bfloat16* Alp = Al_ + zb * sAb + zh * sAh + (size_t)m0 * lda;
    const __nv_bfloat16* Bhp = Bh_ + zb * sBb + zh * sBh + (size_t)n0 * ldb;
    const __nv_bfloat16* Blp = Bl_ + zb * sBb + zh * sBh + (size_t)n0 * ldb;
    const size_t coff = zb * sCb + zh * sCh;

    float acc[2][NTC][4] = {};

    auto stage = [&](int st, int k0) {
        uint32_t dst0 = sbase + st * STAGE;
        #pragma unroll
        for (int p = 0; p < LP; p++) {
            int idx = tid + p * 256;
            int isB = idx >= 1024;
            int s = isB ? idx - 1024 : idx;
            int r = s >> 3, q = s & 7;
            const __nv_bfloat16* src = isB
                ? ((q < 4 ? Bhp : Blp) + (size_t)r * ldb + k0 + (q & 3) * 8)
                : ((q < 4 ? Ahp : Alp) + (size_t)r * lda + k0 + (q & 3) * 8);
            uint32_t dst = dst0 + isB * 16384 + r * 128 + ((q * 16) ^ ((r & 7) * 16));
            cpa16(dst, src);
        }
        asm volatile("cp.async.commit_group;" ::: "memory");
    };

    auto compute = [&](int st) {
        uint32_t sA = sbase + st * STAGE, sB = sA + 16384;
        #pragma unroll
        for (int ks = 0; ks < 2; ks++) {
            uint32_t ah[2][4], al[2][4];
            #pragma unroll
            for (int mt = 0; mt < 2; mt++) {
                int row = wm * 32 + mt * 16 + (lane & 15);
                int kb = ks * 32 + (lane >> 4) * 16;
                uint32_t rb = sA + row * 128;
                uint32_t xr = (row & 7) * 16;
                ldsm4(ah[mt][0], ah[mt][1], ah[mt][2], ah[mt][3], rb + (kb ^ xr));
                ldsm4(al[mt][0], al[mt][1], al[mt][2], al[mt][3], rb + ((kb + 64) ^ xr));
            }
            #pragma unroll
            for (int j = 0; j < NJ; j++) {
                int g = lane >> 3;
                int row = wn * (BN / 2) + (j * 2 + (g >> 1)) * 8 + (lane & 7);
                int kb = ks * 32 + (g & 1) * 16;
                uint32_t rb = sB + row * 128;
                uint32_t xr = (row & 7) * 16;
                uint32_t bh[4], bl[4];
                ldsm4(bh[0], bh[1], bh[2], bh[3], rb + (kb ^ xr));
                ldsm4(bl[0], bl[1], bl[2], bl[3], rb + ((kb + 64) ^ xr));
                #pragma unroll
                for (int mt = 0; mt < 2; mt++) {
                    #pragma unroll
                    for (int t = 0; t < 2; t++) {
                        float* c = acc[mt][j * 2 + t];
                        mma16816(c, ah[mt], bh[2 * t], bh[2 * t + 1]);
                        mma16816(c, ah[mt], bl[2 * t], bl[2 * t + 1]);
                        mma16816(c, al[mt], bh[2 * t], bh[2 * t + 1]);
                    }
                }
            }
        }
    };

    const int NC = K >> 5;
    stage(0, 0);
    for (int c = 0; c < NC; c++) {
        asm volatile("cp.async.wait_group 0;" ::: "memory");
        __syncthreads();
        if (c + 1 < NC) stage((c + 1) & 1, (c + 1) * 32);
        compute(c & 1);
    }

    const int r_in = lane >> 2, c_in = (lane & 3) * 2;
    #pragma unroll
    for (int mt = 0; mt < 2; mt++) {
        #pragma unroll
        for (int rr = 0; rr < 2; rr++) {
            int row = m0 + wm * 32 + mt * 16 + rr * 8 + r_in;
            #pragma unroll
            for (int nt = 0; nt < NTC; nt++) {
                int col = n0 + wn * (BN / 2) + nt * 8 + c_in;
                float v0 = acc[mt][nt][rr * 2 + 0];
                float v1 = acc[mt][nt][rr * 2 + 1];
                if (bias) { v0 += bias[col]; v1 += bias[col + 1]; }
                if (gelu) {
                    v0 = 0.5f * v0 * (1.0f + erff(v0 * 0.7071067811865476f));
                    v1 = 0.5f * v1 * (1.0f + erff(v1 * 0.7071067811865476f));
                }
                size_t off = coff + (size_t)row * ldc + col;
                if (res) {
                    float2 rr2 = *(const float2*)(res + off);
                    v0 += rr2.x; v1 += rr2.y;
                }
                if (Cf) *(float2*)(Cf + off) = make_float2(v0, v1);
                if (Ch) {
                    __nv_bfloat16 h0, l0, h1, l1;
                    split2(v0, h0, l0); split2(v1, h1, l1);
                    *(__nv_bfloat162*)(Ch + off) = __nv_bfloat162(h0, h1);
                    *(__nv_bfloat162*)(Cl + off) = __nv_bfloat162(l0, l1);
                }
            }
        }
    }
}

// ================= fused flash attention (split-bf16, online softmax) ===========
// One CTA = one (z, 128-row Q block). 8 warps x 16 rows, 64-wide KV chunks.
// R12 fixes vs R11: NO register cap (occ 1, ~170 regs, no spills) and
// double-buffered K/V+mask with prefetch issued before compute (overlap).
// SMEM: Q 32KB resident | 2 stages x (K 16KB + V 16KB) | 2 x 256B mask.
constexpr int FQ_OFF = 0, FKV_OFF = 32768, FKV_STAGE = 32768, FM_OFF = 98304;
constexpr int FSMEM = 98816;

template<int CAUSAL>
__global__ __launch_bounds__(256)
void flashattn(const __nv_bfloat16* __restrict__ Qh, const __nv_bfloat16* __restrict__ Ql,
               int ldq, const __nv_bfloat16* __restrict__ Kh, const __nv_bfloat16* __restrict__ Kl,
               int ldk, const __nv_bfloat16* __restrict__ Vth, const __nv_bfloat16* __restrict__ Vtl,
               const float* __restrict__ amask,
               __nv_bfloat16* __restrict__ Ch, __nv_bfloat16* __restrict__ Cl)
{
    extern __shared__ __align__(1024) char smraw[];
    const uint32_t sb = s2u(smraw);
    const int tid = threadIdx.x, lane = tid & 31, wid = tid >> 5;
    const int z = blockIdx.y, b = z >> 4, h = z & 15;
    const int m0 = blockIdx.x * 128;

    const __nv_bfloat16* qbh = Qh + (size_t)b * Sn * ldq + h * 64;
    const __nv_bfloat16* qbl = Ql + (size_t)b * Sn * ldq + h * 64;
    const __nv_bfloat16* kbh = Kh + (size_t)b * Tn * ldk + h * 64;
    const __nv_bfloat16* kbl = Kl + (size_t)b * Tn * ldk + h * 64;
    const __nv_bfloat16* vbh = Vth + (size_t)z * 64 * 1024;
    const __nv_bfloat16* vbl = Vtl + (size_t)z * 64 * 1024;

    const int nch = CAUSAL ? (m0 >> 6) + 2 : 16;

    auto load_kv = [&](int t0, int st) {
        uint32_t base = sb + FKV_OFF + st * FKV_STAGE;
        #pragma unroll
        for (int p = 0; p < 4; p++) {            // K tile: 2 d-chunks x 64 rows
            int idx = tid + p * 256;
            int cc = idx >> 9, s = idx & 511, r = s >> 3, q = s & 7;
            const __nv_bfloat16* src = (q < 4 ? kbh : kbl) + (size_t)(t0 + r) * ldk + cc * 32 + (q & 3) * 8;
            cpa16(base + cc * 8192 + r * 128 + ((q * 16) ^ ((r & 7) * 16)), src);
        }
        #pragma unroll
        for (int p = 0; p < 4; p++) {            // V^T tile: 2 t-chunks x 64 d-rows
            int idx = tid + p * 256;
            int cc = idx >> 9, s = idx & 511, r = s >> 3, q = s & 7;
            const __nv_bfloat16* src = (q < 4 ? vbh : vbl) + (size_t)r * 1024 + t0 + cc * 32 + (q & 3) * 8;
            cpa16(base + 16384 + cc * 8192 + r * 128 + ((q * 16) ^ ((r & 7) * 16)), src);
        }
        if (!CAUSAL && tid < 64)
            cpa4(sb + FM_OFF + st * 256 + tid * 4, amask + (size_t)b * Tn + t0 + tid);
        asm volatile("cp.async.commit_group;" ::: "memory");
    };

    // Q: 2 chunks x 128 rows, resident all kernel
    #pragma unroll
    for (int p = 0; p < 8; p++) {
        int idx = tid + p * 256;
        int cc = idx >> 10, s = idx & 1023, r = s >> 3, q = s & 7;
        const __nv_bfloat16* src = (q < 4 ? qbh : qbl) + (size_t)(m0 + r) * ldq + cc * 32 + (q & 3) * 8;
        cpa16(sb + FQ_OFF + cc * 16384 + r * 128 + ((q * 16) ^ ((r & 7) * 16)), src);
    }
    load_kv(0, 0);

    float o[8][4] = {};
    float mr0 = -1e30f, mr1 = -1e30f, lr0 = 0.f, lr1 = 0.f;
    const int rl = wid * 16 + (lane >> 2);
    const int grow0 = m0 + rl, grow1 = grow0 + 8;
    const int g = lane >> 3;

    for (int t = 0; t < nch; t++) {
        const int t0 = t * 64;
        const int st = t & 1;
        asm volatile("cp.async.wait_group 0;" ::: "memory");
        __syncthreads();
        if (t + 1 < nch) load_kv(t0 + 64, st ^ 1);     // prefetch overlaps compute
        const uint32_t kvb = sb + FKV_OFF + st * FKV_STAGE;
        const float* msk = (const float*)(smraw + FM_OFF + st * 256);

        // ---- S = Q K^T (3-product split) ----
        float s_[8][4] = {};
        #pragma unroll
        for (int ks = 0; ks < 4; ks++) {
            int cc = ks >> 1;
            int arow = wid * 16 + (lane & 15);
            int kba = (ks & 1) * 32 + (lane >> 4) * 16;
            uint32_t Qrb = sb + FQ_OFF + cc * 16384 + arow * 128;
            uint32_t xa = (arow & 7) * 16;
            uint32_t ah[4], al[4];
            ldsm4(ah[0], ah[1], ah[2], ah[3], Qrb + (kba ^ xa));
            ldsm4(al[0], al[1], al[2], al[3], Qrb + ((kba + 64) ^ xa));
            int kbb = (ks & 1) * 32 + (g & 1) * 16;
            #pragma unroll
            for (int j = 0; j < 4; j++) {
                int brow = (j * 2 + (g >> 1)) * 8 + (lane & 7);
                uint32_t Krb = kvb + cc * 8192 + brow * 128;
                uint32_t xb = (brow & 7) * 16;
                uint32_t bh[4], bl[4];
                ldsm4(bh[0], bh[1], bh[2], bh[3], Krb + (kbb ^ xb));
                ldsm4(bl[0], bl[1], bl[2], bl[3], Krb + ((kbb + 64) ^ xb));
                mma16816(s_[2 * j],     ah, bh[0], bh[1]);
                mma16816(s_[2 * j],     ah, bl[0], bl[1]);
                mma16816(s_[2 * j],     al, bh[0], bh[1]);
                mma16816(s_[2 * j + 1], ah, bh[2], bh[3]);
                mma16816(s_[2 * j + 1], ah, bl[2], bl[3]);
                mma16816(s_[2 * j + 1], al, bh[2], bh[3]);
            }
        }

        // ---- scale + mask ----
        #pragma unroll
        for (int nt = 0; nt < 8; nt++) {
            int cl0 = nt * 8 + (lane & 3) * 2;
            if (CAUSAL) {
                int c0 = t0 + cl0;
                s_[nt][0] = (c0     <= grow0) ? s_[nt][0] * SCALE : -1e30f;
                s_[nt][1] = (c0 + 1 <= grow0) ? s_[nt][1] * SCALE : -1e30f;
                s_[nt][2] = (c0     <= grow1) ? s_[nt][2] * SCALE : -1e30f;
                s_[nt][3] = (c0 + 1 <= grow1) ? s_[nt][3] * SCALE : -1e30f;
            } else {
                float mv0 = msk[cl0], mv1 = msk[cl0 + 1];
                s_[nt][0] = s_[nt][0] * SCALE + mv0;
                s_[nt][1] = s_[nt][1] * SCALE + mv1;
                s_[nt][2] = s_[nt][2] * SCALE + mv0;
                s_[nt][3] = s_[nt][3] * SCALE + mv1;
            }
        }

        // ---- online softmax (row stats across quad lanes) ----
        float mx0 = -1e30f, mx1 = -1e30f;
        #pragma unroll
        for (int nt = 0; nt < 8; nt++) {
            mx0 = fmaxf(mx0, fmaxf(s_[nt][0], s_[nt][1]));
            mx1 = fmaxf(mx1, fmaxf(s_[nt][2], s_[nt][3]));
        }
        mx0 = fmaxf(mx0, __shfl_xor_sync(~0u, mx0, 1));
        mx0 = fmaxf(mx0, __shfl_xor_sync(~0u, mx0, 2));
        mx1 = fmaxf(mx1, __shfl_xor_sync(~0u, mx1, 1));
        mx1 = fmaxf(mx1, __shfl_xor_sync(~0u, mx1, 2));
        float mn0 = fmaxf(mr0, mx0), mn1 = fmaxf(mr1, mx1);
        float f0 = __expf(mr0 - mn0), f1 = __expf(mr1 - mn1);
        float sum0 = 0.f, sum1 = 0.f;
        #pragma unroll
        for (int nt = 0; nt < 8; nt++) {
            s_[nt][0] = __expf(s_[nt][0] - mn0);
            s_[nt][1] = __expf(s_[nt][1] - mn0);
            s_[nt][2] = __expf(s_[nt][2] - mn1);
            s_[nt][3] = __expf(s_[nt][3] - mn1);
            sum0 += s_[nt][0] + s_[nt][1];
            sum1 += s_[nt][2] + s_[nt][3];
        }
        sum0 += __shfl_xor_sync(~0u, sum0, 1);
        sum0 += __shfl_xor_sync(~0u, sum0, 2);
        sum1 += __shfl_xor_sync(~0u, sum1, 1);
        sum1 += __shfl_xor_sync(~0u, sum1, 2);
        lr0 = lr0 * f0 + sum0; lr1 = lr1 * f1 + sum1;
        mr0 = mn0; mr1 = mn1;
        #pragma unroll
        for (int nt = 0; nt < 8; nt++) {
            o[nt][0] *= f0; o[nt][1] *= f0; o[nt][2] *= f1; o[nt][3] *= f1;
        }

        // ---- O += P V^T (split P x split V) ----
        #pragma unroll
        for (int ks = 0; ks < 4; ks++) {
            int cc = ks >> 1;
            uint32_t pah[4], pal[4];
            {
                __nv_bfloat16 h0, l0, h1, l1;
                split2(s_[2 * ks][0], h0, l0); split2(s_[2 * ks][1], h1, l1);
                pah[0] = packbf(h0, h1); pal[0] = packbf(l0, l1);
                split2(s_[2 * ks][2], h0, l0); split2(s_[2 * ks][3], h1, l1);
                pah[1] = packbf(h0, h1); pal[1] = packbf(l0, l1);
                split2(s_[2 * ks + 1][0], h0, l0); split2(s_[2 * ks + 1][1], h1, l1);
                pah[2] = packbf(h0, h1); pal[2] = packbf(l0, l1);
                split2(s_[2 * ks + 1][2], h0, l0); split2(s_[2 * ks + 1][3], h1, l1);
                pah[3] = packbf(h0, h1); pal[3] = packbf(l0, l1);
            }
            int kbb = (ks & 1) * 32 + (g & 1) * 16;
            #pragma unroll
            for (int j = 0; j < 4; j++) {
                int brow = (j * 2 + (g >> 1)) * 8 + (lane & 7);
                uint32_t Vrb = kvb + 16384 + cc * 8192 + brow * 128;
                uint32_t xb = (brow & 7) * 16;
                uint32_t bh[4], bl[4];
                ldsm4(bh[0], bh[1], bh[2], bh[3], Vrb + (kbb ^ xb));
                ldsm4(bl[0], bl[1], bl[2], bl[3], Vrb + ((kbb + 64) ^ xb));
                mma16816(o[2 * j],     pah, bh[0], bh[1]);
                mma16816(o[2 * j],     pah, bl[0], bl[1]);
                mma16816(o[2 * j],     pal, bh[0], bh[1]);
                mma16816(o[2 * j + 1], pah, bh[2], bh[3]);
                mma16816(o[2 * j + 1], pah, bl[2], bl[3]);
                mma16816(o[2 * j + 1], pal, bh[2], bh[3]);
            }
        }
    }

    // ---- epilogue: normalize + split write ----
    float i0 = 1.f / lr0, i1 = 1.f / lr1;
    size_t ob0 = (size_t)(b * Sn + grow0) * 1024 + h * 64;
    size_t ob1 = (size_t)(b * Sn + grow1) * 1024 + h * 64;
    #pragma unroll
    for (int nt = 0; nt < 8; nt++) {
        int d = nt * 8 + (lane & 3) * 2;
        __nv_bfloat16 h0, l0, h1, l1;
        split2(o[nt][0] * i0, h0, l0); split2(o[nt][1] * i0, h1, l1);
        *(__nv_bfloat162*)(Ch + ob0 + d) = __nv_bfloat162(h0, h1);
        *(__nv_bfloat162*)(Cl + ob0 + d) = __nv_bfloat162(l0, l1);
        split2(o[nt][2] * i1, h0, l0); split2(o[nt][3] * i1, h1, l1);
        *(__nv_bfloat162*)(Ch + ob1 + d) = __nv_bfloat162(h0, h1);
        *(__nv_bfloat162*)(Cl + ob1 + d) = __nv_bfloat162(l0, l1);
    }
}

// ============== V transpose: vt[z][d][t] = v[(b*S+t)*ld + off + h*64 + d] =======
__global__ __launch_bounds__(256) void vtransT(
    const __nv_bfloat16* __restrict__ inh, const __nv_bfloat16* __restrict__ inl,
    int ld, int off, __nv_bfloat16* __restrict__ oth, __nv_bfloat16* __restrict__ otl)
{
    __shared__ __nv_bfloat16 th[32][33], tl[32][33];
    const int z = blockIdx.z, b = z >> 4, h = z & 15;
    const int t0 = blockIdx.x * 32, d0 = blockIdx.y * 32;
    const int tx = threadIdx.x & 31, ty = threadIdx.x >> 5;
    const __nv_bfloat16* sh = inh + (size_t)b * Sn * ld + off + h * 64 + d0;
    const __nv_bfloat16* sl = inl + (size_t)b * Sn * ld + off + h * 64 + d0;
    #pragma unroll
    for (int i = 0; i < 4; i++) {
        int t = t0 + ty + i * 8;
        th[ty + i * 8][tx] = sh[(size_t)t * ld + tx];
        tl[ty + i * 8][tx] = sl[(size_t)t * ld + tx];
    }
    __syncthreads();
    size_t obase = (size_t)z * 64 * 1024;
    #pragma unroll
    for (int i = 0; i < 4; i++) {
        int d = d0 + ty + i * 8;
        oth[obase + (size_t)d * 1024 + t0 + tx] = th[tx][ty + i * 8];
        otl[obase + (size_t)d * 1024 + t0 + tx] = tl[tx][ty + i * 8];
    }
}

// ============== weight transpose + split: W[K,N] -> Wh/Wl[N,K] bf16 =============
__global__ __launch_bounds__(256) void wsplitT(
    const float* __restrict__ W, __nv_bfloat16* __restrict__ oh,
    __nv_bfloat16* __restrict__ ol, int K, int N)
{
    __shared__ float t[32][33];
    int tx = threadIdx.x & 31, ty = threadIdx.x >> 5;
    int n0 = blockIdx.x * 32, k0 = blockIdx.y * 32;
    #pragma unroll
    for (int i = 0; i < 4; i++)
        t[ty + i * 8][tx] = W[(size_t)(k0 + ty + i * 8) * N + n0 + tx];
    __syncthreads();
    #pragma unroll
    for (int i = 0; i < 4; i++) {
        float v = t[tx][ty + i * 8];
        __nv_bfloat16 h, l;
        split2(v, h, l);
        size_t o = (size_t)(n0 + ty + i * 8) * K + k0 + tx;
        oh[o] = h; ol[o] = l;
    }
}

// ============== elementwise split (enc hidden states) ===========================
__global__ __launch_bounds__(256) void esplit(
    const float* __restrict__ x, __nv_bfloat16* __restrict__ oh,
    __nv_bfloat16* __restrict__ ol)
{
    int i = blockIdx.x * 256 + threadIdx.x;
    float4 v = ((const float4*)x)[i];
    __nv_bfloat16 h0, l0, h1, l1, h2, l2, h3, l3;
    split2(v.x, h0, l0); split2(v.y, h1, l1); split2(v.z, h2, l2); split2(v.w, h3, l3);
    ((__nv_bfloat162*)oh)[2 * i]     = __nv_bfloat162(h0, h1);
    ((__nv_bfloat162*)oh)[2 * i + 1] = __nv_bfloat162(h2, h3);
    ((__nv_bfloat162*)ol)[2 * i]     = __nv_bfloat162(l0, l1);
    ((__nv_bfloat162*)ol)[2 * i + 1] = __nv_bfloat162(l2, l3);
}

// ============== LayerNorm -> split bf16 =========================================
__global__ __launch_bounds__(256) void ln_split(
    const float* __restrict__ x, const float* __restrict__ w,
    const float* __restrict__ bb, __nv_bfloat16* __restrict__ yh,
    __nv_bfloat16* __restrict__ yl)
{
    const int row = blockIdx.x, tid = threadIdx.x;
    float4 v = ((const float4*)(x + (size_t)row * Dn))[tid];
    float s  = v.x + v.y + v.z + v.w;
    float sq = v.x * v.x + v.y * v.y + v.z * v.z + v.w * v.w;

    __shared__ float sm[18];
    #pragma unroll
    for (int off = 16; off > 0; off >>= 1) {
        s  += __shfl_xor_sync(~0u, s,  off);
        sq += __shfl_xor_sync(~0u, sq, off);
    }
    if ((tid & 31) == 0) { sm[tid >> 5] = s; sm[(tid >> 5) + 8] = sq; }
    __syncthreads();
    if (tid < 32) {
        float a  = (tid < 8) ? sm[tid]     : 0.f;
        float aq = (tid < 8) ? sm[tid + 8] : 0.f;
        #pragma unroll
        for (int off = 4; off > 0; off >>= 1) {
            a  += __shfl_xor_sync(~0u, a,  off);
            aq += __shfl_xor_sync(~0u, aq, off);
        }
        if (tid == 0) { sm[16] = a; sm[17] = aq; }
    }
    __syncthreads();
    const float mean = sm[16] * (1.0f / Dn);
    const float var  = sm[17] * (1.0f / Dn) - mean * mean;
    const float rstd = rsqrtf(var + 1e-12f);

    float4 w4 = ((const float4*)w)[tid];
    float4 b4 = ((const float4*)bb)[tid];
    float o0 = w4.x * (v.x - mean) * rstd + b4.x;
    float o1 = w4.y * (v.y - mean) * rstd + b4.y;
    float o2 = w4.z * (v.z - mean) * rstd + b4.z;
    float o3 = w4.w * (v.w - mean) * rstd + b4.w;
    __nv_bfloat16 h0, l0, h1, l1, h2, l2, h3, l3;
    split2(o0, h0, l0); split2(o1, h1, l1); split2(o2, h2, l2); split2(o3, h3, l3);
    size_t base = (size_t)row * Dn + tid * 4;
    ((__nv_bfloat162*)(yh + base))[0] = __nv_bfloat162(h0, h1);
    ((__nv_bfloat162*)(yh + base))[1] = __nv_bfloat162(h2, h3);
    ((__nv_bfloat162*)(yl + base))[0] = __nv_bfloat162(l0, l1);
    ((__nv_bfloat162*)(yl + base))[1] = __nv_bfloat162(l2, l3);
}

// -------------------------------- launcher --------------------------------------
extern "C" void kernel_launch(void* const* d_in, const int* in_sizes, int n_in,
                              void* d_out, int out_size)
{
    const float* hid      = (const float*)d_in[0];
    const float* enc      = (const float*)d_in[1];
    const float* enc_mask = (const float*)d_in[2];
    const float *ln1_w = (const float*)d_in[4],  *ln1_b = (const float*)d_in[5];
    const float *qkv_w = (const float*)d_in[6],  *qkv_b = (const float*)d_in[7];
    const float *ao_w  = (const float*)d_in[8],  *ao_b  = (const float*)d_in[9];
    const float *ln2_w = (const float*)d_in[10], *ln2_b = (const float*)d_in[11];
    const float *q_w   = (const float*)d_in[12], *q_b   = (const float*)d_in[13];
    const float *kv_w  = (const float*)d_in[14], *kv_b  = (const float*)d_in[15];
    const float *co_w  = (const float*)d_in[16], *co_b  = (const float*)d_in[17];
    const float *ln3_w = (const float*)d_in[18], *ln3_b = (const float*)d_in[19];
    const float *fi_w  = (const float*)d_in[20], *fi_b  = (const float*)d_in[21];
    const float *fo_w  = (const float*)d_in[22], *fo_b  = (const float*)d_in[23];
    float* out = (float*)d_out;

    float *hb;
    __nv_bfloat16 *qkvh, *qkvl, *qh, *ql, *kvh, *kvl, *vth, *vtl;
    __nv_bfloat16 *lnh, *lnl, *ctxh, *ctxl, *ench, *encl, *ffnh, *ffnl, *wth, *wtl;
    cudaGetSymbolAddress((void**)&hb,   g_h);
    cudaGetSymbolAddress((void**)&qkvh, g_qkvh);
    cudaGetSymbolAddress((void**)&qkvl, g_qkvl);
    cudaGetSymbolAddress((void**)&qh,   g_qh);
    cudaGetSymbolAddress((void**)&ql,   g_ql);
    cudaGetSymbolAddress((void**)&kvh,  g_kvh);
    cudaGetSymbolAddress((void**)&kvl,  g_kvl);
    cudaGetSymbolAddress((void**)&vth,  g_vth);
    cudaGetSymbolAddress((void**)&vtl,  g_vtl);
    cudaGetSymbolAddress((void**)&lnh,  g_lnh);
    cudaGetSymbolAddress((void**)&lnl,  g_lnl);
    cudaGetSymbolAddress((void**)&ctxh, g_ctxh);
    cudaGetSymbolAddress((void**)&ctxl, g_ctxl);
    cudaGetSymbolAddress((void**)&ench, g_ench);
    cudaGetSymbolAddress((void**)&encl, g_encl);
    cudaGetSymbolAddress((void**)&ffnh, g_ffnh);
    cudaGetSymbolAddress((void**)&ffnl, g_ffnl);
    cudaGetSymbolAddress((void**)&wth,  g_wth);
    cudaGetSymbolAddress((void**)&wtl,  g_wtl);

    static bool attr_done = false;
    if (!attr_done) {
        cudaFuncSetAttribute(tgemm<128>, cudaFuncAttributeMaxDynamicSharedMemorySize, 65536);
        cudaFuncSetAttribute(flashattn<0>, cudaFuncAttributeMaxDynamicSharedMemorySize, FSMEM);
        cudaFuncSetAttribute(flashattn<1>, cudaFuncAttributeMaxDynamicSharedMemorySize, FSMEM);
        attr_done = true;
    }
    const int SM128 = 65536;
    const int M = Mrows;  // 4096

    // ---- weight conversion (transpose + split) ----
    wsplitT<<<dim3(3072 / 32, 1024 / 32), 256>>>(qkv_w, wth + OW_QKV, wtl + OW_QKV, 1024, 3072);
    wsplitT<<<dim3(1024 / 32, 1024 / 32), 256>>>(ao_w,  wth + OW_AO,  wtl + OW_AO,  1024, 1024);
    wsplitT<<<dim3(1024 / 32, 1024 / 32), 256>>>(q_w,   wth + OW_Q,   wtl + OW_Q,   1024, 1024);
    wsplitT<<<dim3(2048 / 32, 1024 / 32), 256>>>(kv_w,  wth + OW_KV,  wtl + OW_KV,  1024, 2048);
    wsplitT<<<dim3(1024 / 32, 1024 / 32), 256>>>(co_w,  wth + OW_CO,  wtl + OW_CO,  1024, 1024);
    wsplitT<<<dim3(4096 / 32, 1024 / 32), 256>>>(fi_w,  wth + OW_FI,  wtl + OW_FI,  1024, 4096);
    wsplitT<<<dim3(1024 / 32, 4096 / 32), 256>>>(fo_w,  wth + OW_FO,  wtl + OW_FO,  4096, 1024);
    esplit<<<(M * Dn / 4) / 256, 256>>>(enc, ench, encl);

    // ==== self-attention block ====
    ln_split<<<M, 256>>>(hid, ln1_w, ln1_b, lnh, lnl);
    tgemm<128><<<dim3(24, M / 128, 1), 256, SM128>>>(
        lnh, lnl, 1024, 0, 0, wth + OW_QKV, wtl + OW_QKV, 1024, 0, 0,
        qkv_b, nullptr, nullptr, qkvh, qkvl, 3072, 0, 0, 1024, 0);
    vtransT<<<dim3(32, 2, 64), 256>>>(qkvh, qkvl, 3072, 2048, vth, vtl);
    flashattn<1><<<dim3(8, 64), 256, FSMEM>>>(
        qkvh, qkvl, 3072, qkvh + 1024, qkvl + 1024, 3072, vth, vtl,
        nullptr, ctxh, ctxl);
    tgemm<128><<<dim3(8, M / 128, 1), 256, SM128>>>(
        ctxh, ctxl, 1024, 0, 0, wth + OW_AO, wtl + OW_AO, 1024, 0, 0,
        ao_b, hid, hb, nullptr, nullptr, 1024, 0, 0, 1024, 0);

    // ==== cross-attention block ====
    ln_split<<<M, 256>>>(hb, ln2_w, ln2_b, lnh, lnl);
    tgemm<128><<<dim3(8, M / 128, 1), 256, SM128>>>(
        lnh, lnl, 1024, 0, 0, wth + OW_Q, wtl + OW_Q, 1024, 0, 0,
        q_b, nullptr, nullptr, qh, ql, 1024, 0, 0, 1024, 0);
    tgemm<128><<<dim3(16, M / 128, 1), 256, SM128>>>(
        ench, encl, 1024, 0, 0, wth + OW_KV, wtl + OW_KV, 1024, 0, 0,
        kv_b, nullptr, nullptr, kvh, kvl, 2048, 0, 0, 1024, 0);
    vtransT<<<dim3(32, 2, 64), 256>>>(kvh, kvl, 2048, 1024, vth, vtl);
    flashattn<0><<<dim3(8, 64), 256, FSMEM>>>(
        qh, ql, 1024, kvh, kvl, 2048, vth, vtl,
        enc_mask, ctxh, ctxl);
    tgemm<128><<<dim3(8, M / 128, 1), 256, SM128>>>(
        ctxh, ctxl, 1024, 0, 0, wth + OW_CO, wtl + OW_CO, 1024, 0, 0,
        co_b, hb, hb, nullptr, nullptr, 1024, 0, 0, 1024, 0);

    // ==== FFN block ====
    ln_split<<<M, 256>>>(hb, ln3_w, ln3_b, lnh, lnl);
    tgemm<128><<<dim3(32, M / 128, 1), 256, SM128>>>(
        lnh, lnl, 1024, 0, 0, wth + OW_FI, wtl + OW_FI, 1024, 0, 0,
        fi_b, nullptr, nullptr, ffnh, ffnl, 4096, 0, 0, 1024, 1);
    tgemm<128><<<dim3(8, M / 128, 1), 256, SM128>>>(
        ffnh, ffnl, 4096, 0, 0, wth + OW_FO, wtl + OW_FO, 4096, 0, 0,
        fo_b, hb, out, nullptr, nullptr, 1024, 0, 0, 4096, 0);
}

// round 15
// speedup vs baseline: 1.3356x; 1.3356x over previous
#include <cuda_runtime.h>
#include <cuda_bf16.h>
#include <math.h>
#include <stdint.h>

// Problem constants
constexpr int Bn = 4, Sn = 1024, Tn = 1024, Dn = 1024, Fn = 4096;
constexpr int Mrows = Bn * Sn;           // 4096
constexpr float SCALE = 0.125f;          // 1/sqrt(64)

// ---------------- scratch (static device globals: allocation-free) -------------
__device__ __align__(256) float g_sc [(size_t)64 * Sn * Tn];   // 256 MB scores
__device__ __align__(256) float g_h  [Mrows * Dn];             // fp32 hidden

__device__ __align__(256) __nv_bfloat16 g_qkvh[Mrows * 3 * Dn];
__device__ __align__(256) __nv_bfloat16 g_qkvl[Mrows * 3 * Dn];
__device__ __align__(256) __nv_bfloat16 g_qh  [Mrows * Dn];
__device__ __align__(256) __nv_bfloat16 g_ql  [Mrows * Dn];
__device__ __align__(256) __nv_bfloat16 g_kvh [Mrows * 2 * Dn];
__device__ __align__(256) __nv_bfloat16 g_kvl [Mrows * 2 * Dn];
__device__ __align__(256) __nv_bfloat16 g_ph  [(size_t)64 * Sn * Tn];
__device__ __align__(256) __nv_bfloat16 g_pl  [(size_t)64 * Sn * Tn];
__device__ __align__(256) __nv_bfloat16 g_vth [64 * 64 * 1024];
__device__ __align__(256) __nv_bfloat16 g_vtl [64 * 64 * 1024];

__device__ __align__(256) __nv_bfloat16 g_lnh [Mrows * Dn];
__device__ __align__(256) __nv_bfloat16 g_lnl [Mrows * Dn];
__device__ __align__(256) __nv_bfloat16 g_ctxh[Mrows * Dn];
__device__ __align__(256) __nv_bfloat16 g_ctxl[Mrows * Dn];
__device__ __align__(256) __nv_bfloat16 g_ench[Mrows * Dn];
__device__ __align__(256) __nv_bfloat16 g_encl[Mrows * Dn];
__device__ __align__(256) __nv_bfloat16 g_ffnh[(size_t)Mrows * Fn];
__device__ __align__(256) __nv_bfloat16 g_ffnl[(size_t)Mrows * Fn];
__device__ __align__(256) __nv_bfloat16 g_wth[16 * 1024 * 1024];
__device__ __align__(256) __nv_bfloat16 g_wtl[16 * 1024 * 1024];
constexpr size_t OW_QKV = 0;
constexpr size_t OW_AO  = OW_QKV + 3u*1024*1024;
constexpr size_t OW_Q   = OW_AO  + 1u*1024*1024;
constexpr size_t OW_KV  = OW_Q   + 1u*1024*1024;
constexpr size_t OW_CO  = OW_KV  + 2u*1024*1024;
constexpr size_t OW_FI  = OW_CO  + 1u*1024*1024;
constexpr size_t OW_FO  = OW_FI  + 4u*1024*1024;

// ================= helpers ======================================================
__device__ __forceinline__ uint32_t s2u(const void* p) {
    uint32_t a;
    asm("{ .reg .u64 t; cvta.to.shared.u64 t, %1; cvt.u32.u64 %0, t; }" : "=r"(a) : "l"(p));
    return a;
}
__device__ __forceinline__ void ldsm4(uint32_t& r0, uint32_t& r1, uint32_t& r2, uint32_t& r3,
                                      uint32_t a) {
    asm volatile("ldmatrix.sync.aligned.m8n8.x4.shared.b16 {%0,%1,%2,%3}, [%4];"
        : "=r"(r0), "=r"(r1), "=r"(r2), "=r"(r3) : "r"(a));
}
__device__ __forceinline__ void mma16816(float* c, const uint32_t* a, uint32_t b0, uint32_t b1) {
    asm volatile(
        "mma.sync.aligned.m16n8k16.row.col.f32.bf16.bf16.f32 "
        "{%0,%1,%2,%3}, {%4,%5,%6,%7}, {%8,%9}, {%0,%1,%2,%3};"
        : "+f"(c[0]), "+f"(c[1]), "+f"(c[2]), "+f"(c[3])
        : "r"(a[0]), "r"(a[1]), "r"(a[2]), "r"(a[3]), "r"(b0), "r"(b1));
}
__device__ __forceinline__ void cpa16(uint32_t dst, const void* src) {
    asm volatile("cp.async.ca.shared.global [%0], [%1], 16;" :: "r"(dst), "l"(src));
}
__device__ __forceinline__ void split2(float x, __nv_bfloat16& h, __nv_bfloat16& l) {
    h = __float2bfloat16(x);
    l = __float2bfloat16(x - __bfloat162float(h));
}

// ================= tensor-core split-bf16 GEMM (mma.sync HMMA) ==================
// Batched: z = blockIdx.z, b=z>>4, h=z&15; operand offset = b*sXb + h*sXh.
// A split [*,K] (row stride lda), B split [N,K] (row stride ldb), both K-major.
// C = A@B^T (+bias)(+GELU)(+res); outputs fp32 (Cf) and/or split bf16 (Ch/Cl).
// trimask: skip tiles fully above the causal diagonal. kcausal: clamp K to the
// 128-row block's causal frontier. __launch_bounds__(256,2): two CTAs co-reside
// per SM so one CTA's MMAs hide the other's cp.async wait + barrier latency.
template<int BN>
__global__ __launch_bounds__(256, 2)
void tgemm(const __nv_bfloat16* __restrict__ Ah_, const __nv_bfloat16* __restrict__ Al_,
           int lda, size_t sAb, size_t sAh,
           const __nv_bfloat16* __restrict__ Bh_, const __nv_bfloat16* __restrict__ Bl_,
           int ldb, size_t sBb, size_t sBh,
           const float* __restrict__ bias, const float* __restrict__ res,
           float* __restrict__ Cf, __nv_bfloat16* __restrict__ Ch, __nv_bfloat16* __restrict__ Cl,
           int ldc, size_t sCb, size_t sCh,
           int K, int gelu, int trimask, int kcausal)
{
    constexpr int STAGE = 16384 + BN * 128;      // bytes per pipeline stage
    constexpr int LP    = (128 + BN) * 8 / 256;  // 16B loads per thread per stage
    constexpr int NTC   = BN / 16;               // 8-col n-tiles per warp
    constexpr int NJ    = BN / 32;               // ldsm-b iterations

    extern __shared__ __align__(1024) char smraw[];
    const uint32_t sbase = s2u(smraw);
    const int tid = threadIdx.x, lane = tid & 31, wid = tid >> 5;
    const int z = blockIdx.z, zb = z >> 4, zh = z & 15;
    const int m0 = blockIdx.y * 128, n0 = blockIdx.x * BN;
    const int wm = wid & 3, wn = wid >> 2;

    if (trimask && n0 > m0 + 127) return;        // fully-masked causal tile
    const int Ke = kcausal ? min(K, ((m0 >> 8) + 1) << 8) : K;

    const __nv_bfloat16* Ahp = Ah_ + zb * sAb + zh * sAh + (size_t)m0 * lda;
    const __nv_bfloat16* Alp = Al_ + zb * sAb + zh * sAh + (size_t)m0 * lda;
    const __nv_bfloat16* Bhp = Bh_ + zb * sBb + zh * sBh + (size_t)n0 * ldb;
    const __nv_bfloat16* Blp = Bl_ + zb * sBb + zh * sBh + (size_t)n0 * ldb;
    const size_t coff = zb * sCb + zh * sCh;

    float acc[2][NTC][4] = {};

    auto stage = [&](int st, int k0) {
        uint32_t dst0 = sbase + st * STAGE;
        #pragma unroll
        for (int p = 0; p < LP; p++) {
            int idx = tid + p * 256;
            int isB = idx >= 1024;
            int s = isB ? idx - 1024 : idx;
            int r = s >> 3, q = s & 7;
            const __nv_bfloat16* src = isB
                ? ((q < 4 ? Bhp : Blp) + (size_t)r * ldb + k0 + (q & 3) * 8)
                : ((q < 4 ? Ahp : Alp) + (size_t)r * lda + k0 + (q & 3) * 8);
            uint32_t dst = dst0 + isB * 16384 + r * 128 + ((q * 16) ^ ((r & 7) * 16));
            cpa16(dst, src);
        }
        asm volatile("cp.async.commit_group;" ::: "memory");
    };

    auto compute = [&](int st) {
        uint32_t sA = sbase + st * STAGE, sB = sA + 16384;
        #pragma unroll
        for (int ks = 0; ks < 2; ks++) {
            uint32_t ah[2][4], al[2][4];
            #pragma unroll
            for (int mt = 0; mt < 2; mt++) {
                int row = wm * 32 + mt * 16 + (lane & 15);
                int kb = ks * 32 + (lane >> 4) * 16;
                uint32_t rb = sA + row * 128;
                uint32_t xr = (row & 7) * 16;
                ldsm4(ah[mt][0], ah[mt][1], ah[mt][2], ah[mt][3], rb + (kb ^ xr));
                ldsm4(al[mt][0], al[mt][1], al[mt][2], al[mt][3], rb + ((kb + 64) ^ xr));
            }
            #pragma unroll
            for (int j = 0; j < NJ; j++) {
                int g = lane >> 3;
                int row = wn * (BN / 2) + (j * 2 + (g >> 1)) * 8 + (lane & 7);
                int kb = ks * 32 + (g & 1) * 16;
                uint32_t rb = sB + row * 128;
                uint32_t xr = (row & 7) * 16;
                uint32_t bh[4], bl[4];
                ldsm4(bh[0], bh[1], bh[2], bh[3], rb + (kb ^ xr));
                ldsm4(bl[0], bl[1], bl[2], bl[3], rb + ((kb + 64) ^ xr));
                #pragma unroll
                for (int mt = 0; mt < 2; mt++) {
                    #pragma unroll
                    for (int t = 0; t < 2; t++) {
                        float* c = acc[mt][j * 2 + t];
                        mma16816(c, ah[mt], bh[2 * t], bh[2 * t + 1]);
                        mma16816(c, ah[mt], bl[2 * t], bl[2 * t + 1]);
                        mma16816(c, al[mt], bh[2 * t], bh[2 * t + 1]);
                    }
                }
            }
        }
    };

    const int NC = Ke >> 5;
    stage(0, 0);
    for (int c = 0; c < NC; c++) {
        asm volatile("cp.async.wait_group 0;" ::: "memory");
        __syncthreads();
        if (c + 1 < NC) stage((c + 1) & 1, (c + 1) * 32);
        compute(c & 1);
    }

    // ---- epilogue ----
    const int r_in = lane >> 2, c_in = (lane & 3) * 2;
    #pragma unroll
    for (int mt = 0; mt < 2; mt++) {
        #pragma unroll
        for (int rr = 0; rr < 2; rr++) {
            int row = m0 + wm * 32 + mt * 16 + rr * 8 + r_in;
            #pragma unroll
            for (int nt = 0; nt < NTC; nt++) {
                int col = n0 + wn * (BN / 2) + nt * 8 + c_in;
                float v0 = acc[mt][nt][rr * 2 + 0];
                float v1 = acc[mt][nt][rr * 2 + 1];
                if (bias) { v0 += bias[col]; v1 += bias[col + 1]; }
                if (gelu) {
                    v0 = 0.5f * v0 * (1.0f + erff(v0 * 0.7071067811865476f));
                    v1 = 0.5f * v1 * (1.0f + erff(v1 * 0.7071067811865476f));
                }
                size_t off = coff + (size_t)row * ldc + col;
                if (res) {
                    float2 rr2 = *(const float2*)(res + off);
                    v0 += rr2.x; v1 += rr2.y;
                }
                if (Cf) *(float2*)(Cf + off) = make_float2(v0, v1);
                if (Ch) {
                    __nv_bfloat16 h0, l0, h1, l1;
                    split2(v0, h0, l0); split2(v1, h1, l1);
                    *(__nv_bfloat162*)(Ch + off) = __nv_bfloat162(h0, h1);
                    *(__nv_bfloat162*)(Cl + off) = __nv_bfloat162(l0, l1);
                }
            }
        }
    }
}

// ============== V transpose: vt[z][d][t] = v[(b*S+t)*ld + off + h*64 + d] =======
__global__ __launch_bounds__(256) void vtransT(
    const __nv_bfloat16* __restrict__ inh, const __nv_bfloat16* __restrict__ inl,
    int ld, int off, __nv_bfloat16* __restrict__ oth, __nv_bfloat16* __restrict__ otl)
{
    __shared__ __nv_bfloat16 th[32][33], tl[32][33];
    const int z = blockIdx.z, b = z >> 4, h = z & 15;
    const int t0 = blockIdx.x * 32, d0 = blockIdx.y * 32;
    const int tx = threadIdx.x & 31, ty = threadIdx.x >> 5;
    const __nv_bfloat16* sh = inh + (size_t)b * Sn * ld + off + h * 64 + d0;
    const __nv_bfloat16* sl = inl + (size_t)b * Sn * ld + off + h * 64 + d0;
    #pragma unroll
    for (int i = 0; i < 4; i++) {
        int t = t0 + ty + i * 8;
        th[ty + i * 8][tx] = sh[(size_t)t * ld + tx];
        tl[ty + i * 8][tx] = sl[(size_t)t * ld + tx];
    }
    __syncthreads();
    size_t obase = (size_t)z * 64 * 1024;
    #pragma unroll
    for (int i = 0; i < 4; i++) {
        int d = d0 + ty + i * 8;
        oth[obase + (size_t)d * 1024 + t0 + tx] = th[tx][ty + i * 8];
        otl[obase + (size_t)d * 1024 + t0 + tx] = tl[tx][ty + i * 8];
    }
}

// ============== weight transpose + split: W[K,N] -> Wh/Wl[N,K] bf16 =============
__global__ __launch_bounds__(256) void wsplitT(
    const float* __restrict__ W, __nv_bfloat16* __restrict__ oh,
    __nv_bfloat16* __restrict__ ol, int K, int N)
{
    __shared__ float t[32][33];
    int tx = threadIdx.x & 31, ty = threadIdx.x >> 5;
    int n0 = blockIdx.x * 32, k0 = blockIdx.y * 32;
    #pragma unroll
    for (int i = 0; i < 4; i++)
        t[ty + i * 8][tx] = W[(size_t)(k0 + ty + i * 8) * N + n0 + tx];
    __syncthreads();
    #pragma unroll
    for (int i = 0; i < 4; i++) {
        float v = t[tx][ty + i * 8];
        __nv_bfloat16 h, l;
        split2(v, h, l);
        size_t o = (size_t)(n0 + ty + i * 8) * K + k0 + tx;
        oh[o] = h; ol[o] = l;
    }
}

// ============== elementwise split (enc hidden states) ===========================
__global__ __launch_bounds__(256) void esplit(
    const float* __restrict__ x, __nv_bfloat16* __restrict__ oh,
    __nv_bfloat16* __restrict__ ol)
{
    int i = blockIdx.x * 256 + threadIdx.x;
    float4 v = ((const float4*)x)[i];
    __nv_bfloat16 h0, l0, h1, l1, h2, l2, h3, l3;
    split2(v.x, h0, l0); split2(v.y, h1, l1); split2(v.z, h2, l2); split2(v.w, h3, l3);
    ((__nv_bfloat162*)oh)[2 * i]     = __nv_bfloat162(h0, h1);
    ((__nv_bfloat162*)oh)[2 * i + 1] = __nv_bfloat162(h2, h3);
    ((__nv_bfloat162*)ol)[2 * i]     = __nv_bfloat162(l0, l1);
    ((__nv_bfloat162*)ol)[2 * i + 1] = __nv_bfloat162(l2, l3);
}

// ============== LayerNorm -> split bf16 =========================================
__global__ __launch_bounds__(256) void ln_split(
    const float* __restrict__ x, const float* __restrict__ w,
    const float* __restrict__ bb, __nv_bfloat16* __restrict__ yh,
    __nv_bfloat16* __restrict__ yl)
{
    const int row = blockIdx.x, tid = threadIdx.x;
    float4 v = ((const float4*)(x + (size_t)row * Dn))[tid];
    float s  = v.x + v.y + v.z + v.w;
    float sq = v.x * v.x + v.y * v.y + v.z * v.z + v.w * v.w;

    __shared__ float sm[18];
    #pragma unroll
    for (int off = 16; off > 0; off >>= 1) {
        s  += __shfl_xor_sync(~0u, s,  off);
        sq += __shfl_xor_sync(~0u, sq, off);
    }
    if ((tid & 31) == 0) { sm[tid >> 5] = s; sm[(tid >> 5) + 8] = sq; }
    __syncthreads();
    if (tid < 32) {
        float a  = (tid < 8) ? sm[tid]     : 0.f;
        float aq = (tid < 8) ? sm[tid + 8] : 0.f;
        #pragma unroll
        for (int off = 4; off > 0; off >>= 1) {
            a  += __shfl_xor_sync(~0u, a,  off);
            aq += __shfl_xor_sync(~0u, aq, off);
        }
        if (tid == 0) { sm[16] = a; sm[17] = aq; }
    }
    __syncthreads();
    const float mean = sm[16] * (1.0f / Dn);
    const float var  = sm[17] * (1.0f / Dn) - mean * mean;
    const float rstd = rsqrtf(var + 1e-12f);

    float4 w4 = ((const float4*)w)[tid];
    float4 b4 = ((const float4*)bb)[tid];
    float o0 = w4.x * (v.x - mean) * rstd + b4.x;
    float o1 = w4.y * (v.y - mean) * rstd + b4.y;
    float o2 = w4.z * (v.z - mean) * rstd + b4.z;
    float o3 = w4.w * (v.w - mean) * rstd + b4.w;
    __nv_bfloat16 h0, l0, h1, l1, h2, l2, h3, l3;
    split2(o0, h0, l0); split2(o1, h1, l1); split2(o2, h2, l2); split2(o3, h3, l3);
    size_t base = (size_t)row * Dn + tid * 4;
    ((__nv_bfloat162*)(yh + base))[0] = __nv_bfloat162(h0, h1);
    ((__nv_bfloat162*)(yh + base))[1] = __nv_bfloat162(h2, h3);
    ((__nv_bfloat162*)(yl + base))[0] = __nv_bfloat162(l0, l1);
    ((__nv_bfloat162*)(yl + base))[1] = __nv_bfloat162(l2, l3);
}

// ============== softmax: fp32 scores -> split-bf16 probs ========================
// causal: only process cols <= s (256-col chunks); masked cols get prob 0
// (matches reference: score -10000 -> exp underflows to exactly 0).
__global__ __launch_bounds__(256) void softmax_split(
    const float* __restrict__ sc, float scale, int causal,
    const float* __restrict__ addmask,
    __nv_bfloat16* __restrict__ ph, __nv_bfloat16* __restrict__ pl)
{
    const int row = blockIdx.x;
    const int s = row & (Sn - 1);
    const int b = row >> 14;
    const float* p = sc + (size_t)row * Tn;
    const int tid = threadIdx.x;

    const int ni = causal ? (s >> 8) + 1 : 4;   // 256-col chunks to process

    float vals[4];
    float mx = -1e30f;
    for (int i = 0; i < ni; i++) {
        int c = tid + i * 256;
        float v;
        if (causal && c > s) v = -10000.0f;
        else {
            v = p[c] * scale;
            if (!causal && addmask) v += addmask[(size_t)b * Tn + c];
        }
        vals[i] = v;
        mx = fmaxf(mx, v);
    }
    __shared__ float sm[18];
    #pragma unroll
    for (int off = 16; off > 0; off >>= 1) mx = fmaxf(mx, __shfl_xor_sync(~0u, mx, off));
    if ((tid & 31) == 0) sm[tid >> 5] = mx;
    __syncthreads();
    if (tid < 32) {
        float a = (tid < 8) ? sm[tid] : -1e30f;
        #pragma unroll
        for (int off = 4; off > 0; off >>= 1) a = fmaxf(a, __shfl_xor_sync(~0u, a, off));
        if (tid == 0) sm[16] = a;
    }
    __syncthreads();
    const float m = sm[16];

    float sum = 0.f;
    for (int i = 0; i < ni; i++) { vals[i] = expf(vals[i] - m); sum += vals[i]; }
    #pragma unroll
    for (int off = 16; off > 0; off >>= 1) sum += __shfl_xor_sync(~0u, sum, off);
    if ((tid & 31) == 0) sm[tid >> 5] = sum;
    __syncthreads();
    if (tid < 32) {
        float a = (tid < 8) ? sm[tid] : 0.f;
        #pragma unroll
        for (int off = 4; off > 0; off >>= 1) a += __shfl_xor_sync(~0u, a, off);
        if (tid == 0) sm[17] = a;
    }
    __syncthreads();
    const float inv = 1.0f / sm[17];
    for (int i = 0; i < ni; i++) {
        int c = tid + i * 256;
        __nv_bfloat16 hh, ll;
        split2(vals[i] * inv, hh, ll);
        ph[(size_t)row * Tn + c] = hh;
        pl[(size_t)row * Tn + c] = ll;
    }
}

// -------------------------------- launcher --------------------------------------
extern "C" void kernel_launch(void* const* d_in, const int* in_sizes, int n_in,
                              void* d_out, int out_size)
{
    const float* hid      = (const float*)d_in[0];
    const float* enc      = (const float*)d_in[1];
    const float* enc_mask = (const float*)d_in[2];
    const float *ln1_w = (const float*)d_in[4],  *ln1_b = (const float*)d_in[5];
    const float *qkv_w = (const float*)d_in[6],  *qkv_b = (const float*)d_in[7];
    const float *ao_w  = (const float*)d_in[8],  *ao_b  = (const float*)d_in[9];
    const float *ln2_w = (const float*)d_in[10], *ln2_b = (const float*)d_in[11];
    const float *q_w   = (const float*)d_in[12], *q_b   = (const float*)d_in[13];
    const float *kv_w  = (const float*)d_in[14], *kv_b  = (const float*)d_in[15];
    const float *co_w  = (const float*)d_in[16], *co_b  = (const float*)d_in[17];
    const float *ln3_w = (const float*)d_in[18], *ln3_b = (const float*)d_in[19];
    const float *fi_w  = (const float*)d_in[20], *fi_b  = (const float*)d_in[21];
    const float *fo_w  = (const float*)d_in[22], *fo_b  = (const float*)d_in[23];
    float* out = (float*)d_out;

    float *sc, *hb;
    __nv_bfloat16 *qkvh, *qkvl, *qh, *ql, *kvh, *kvl, *ph, *pl, *vth, *vtl;
    __nv_bfloat16 *lnh, *lnl, *ctxh, *ctxl, *ench, *encl, *ffnh, *ffnl, *wth, *wtl;
    cudaGetSymbolAddress((void**)&sc,   g_sc);
    cudaGetSymbolAddress((void**)&hb,   g_h);
    cudaGetSymbolAddress((void**)&qkvh, g_qkvh);
    cudaGetSymbolAddress((void**)&qkvl, g_qkvl);
    cudaGetSymbolAddress((void**)&qh,   g_qh);
    cudaGetSymbolAddress((void**)&ql,   g_ql);
    cudaGetSymbolAddress((void**)&kvh,  g_kvh);
    cudaGetSymbolAddress((void**)&kvl,  g_kvl);
    cudaGetSymbolAddress((void**)&ph,   g_ph);
    cudaGetSymbolAddress((void**)&pl,   g_pl);
    cudaGetSymbolAddress((void**)&vth,  g_vth);
    cudaGetSymbolAddress((void**)&vtl,  g_vtl);
    cudaGetSymbolAddress((void**)&lnh,  g_lnh);
    cudaGetSymbolAddress((void**)&lnl,  g_lnl);
    cudaGetSymbolAddress((void**)&ctxh, g_ctxh);
    cudaGetSymbolAddress((void**)&ctxl, g_ctxl);
    cudaGetSymbolAddress((void**)&ench, g_ench);
    cudaGetSymbolAddress((void**)&encl, g_encl);
    cudaGetSymbolAddress((void**)&ffnh, g_ffnh);
    cudaGetSymbolAddress((void**)&ffnl, g_ffnl);
    cudaGetSymbolAddress((void**)&wth,  g_wth);
    cudaGetSymbolAddress((void**)&wtl,  g_wtl);

    static bool init_done = false;
    static cudaStream_t s2;
    static cudaEvent_t e_fork, e_join;
    if (!init_done) {
        cudaFuncSetAttribute(tgemm<128>, cudaFuncAttributeMaxDynamicSharedMemorySize, 65536);
        cudaFuncSetAttribute(tgemm<64>,  cudaFuncAttributeMaxDynamicSharedMemorySize, 49152);
        cudaStreamCreateWithFlags(&s2, cudaStreamNonBlocking);
        cudaEventCreateWithFlags(&e_fork, cudaEventDisableTiming);
        cudaEventCreateWithFlags(&e_join, cudaEventDisableTiming);
        init_done = true;
    }
    const int SM128 = 65536, SM64 = 49152;
    const int M = Mrows;  // 4096
    const size_t ZST = (size_t)Sn * Tn;

    // ---- weight prep: QKV (critical path) on main; rest forked onto s2 ----
    wsplitT<<<dim3(3072 / 32, 1024 / 32), 256>>>(qkv_w, wth + OW_QKV, wtl + OW_QKV, 1024, 3072);
    cudaEventRecord(e_fork, 0);
    cudaStreamWaitEvent(s2, e_fork, 0);
    wsplitT<<<dim3(1024 / 32, 1024 / 32), 256, 0, s2>>>(ao_w,  wth + OW_AO,  wtl + OW_AO,  1024, 1024);
    wsplitT<<<dim3(1024 / 32, 1024 / 32), 256, 0, s2>>>(q_w,   wth + OW_Q,   wtl + OW_Q,   1024, 1024);
    wsplitT<<<dim3(2048 / 32, 1024 / 32), 256, 0, s2>>>(kv_w,  wth + OW_KV,  wtl + OW_KV,  1024, 2048);
    wsplitT<<<dim3(1024 / 32, 1024 / 32), 256, 0, s2>>>(co_w,  wth + OW_CO,  wtl + OW_CO,  1024, 1024);
    wsplitT<<<dim3(4096 / 32, 1024 / 32), 256, 0, s2>>>(fi_w,  wth + OW_FI,  wtl + OW_FI,  1024, 4096);
    wsplitT<<<dim3(1024 / 32, 4096 / 32), 256, 0, s2>>>(fo_w,  wth + OW_FO,  wtl + OW_FO,  4096, 1024);
    esplit<<<(M * Dn / 4) / 256, 256, 0, s2>>>(enc, ench, encl);
    cudaEventRecord(e_join, s2);

    // ==== self-attention block (overlaps with s2 prep) ====
    ln_split<<<M, 256>>>(hid, ln1_w, ln1_b, lnh, lnl);
    tgemm<128><<<dim3(24, M / 128, 1), 256, SM128>>>(
        lnh, lnl, 1024, 0, 0, wth + OW_QKV, wtl + OW_QKV, 1024, 0, 0,
        qkv_b, nullptr, nullptr, qkvh, qkvl, 3072, 0, 0, 1024, 0, 0, 0);
    vtransT<<<dim3(32, 2, 64), 256>>>(qkvh, qkvl, 3072, 2048, vth, vtl);
    tgemm<128><<<dim3(8, 8, 64), 256, SM128>>>(                       // scores = Q.K^T
        qkvh, qkvl, 3072, (size_t)Sn * 3072, 64,
        qkvh + 1024, qkvl + 1024, 3072, (size_t)Sn * 3072, 64,
        nullptr, nullptr, sc, nullptr, nullptr, 1024, 16 * ZST, ZST, 64, 0, 1, 0);
    softmax_split<<<64 * Sn, 256>>>(sc, SCALE, 1, nullptr, ph, pl);
    tgemm<64><<<dim3(1, 8, 64), 256, SM64>>>(                          // ctx = P.V
        ph, pl, 1024, 16 * ZST, ZST,
        vth, vtl, 1024, (size_t)16 * 64 * 1024, (size_t)64 * 1024,
        nullptr, nullptr, nullptr, ctxh, ctxl, 1024, (size_t)Sn * Dn, 64, 1024, 0, 0, 1);

    cudaStreamWaitEvent(0, e_join, 0);   // need OW_AO (and later weights/enc split)
    tgemm<128><<<dim3(8, M / 128, 1), 256, SM128>>>(
        ctxh, ctxl, 1024, 0, 0, wth + OW_AO, wtl + OW_AO, 1024, 0, 0,
        ao_b, hid, hb, nullptr, nullptr, 1024, 0, 0, 1024, 0, 0, 0);

    // ==== cross-attention block ====
    ln_split<<<M, 256>>>(hb, ln2_w, ln2_b, lnh, lnl);
    tgemm<128><<<dim3(8, M / 128, 1), 256, SM128>>>(
        lnh, lnl, 1024, 0, 0, wth + OW_Q, wtl + OW_Q, 1024, 0, 0,
        q_b, nullptr, nullptr, qh, ql, 1024, 0, 0, 1024, 0, 0, 0);
    tgemm<128><<<dim3(16, M / 128, 1), 256, SM128>>>(
        ench, encl, 1024, 0, 0, wth + OW_KV, wtl + OW_KV, 1024, 0, 0,
        kv_b, nullptr, nullptr, kvh, kvl, 2048, 0, 0, 1024, 0, 0, 0);
    vtransT<<<dim3(32, 2, 64), 256>>>(kvh, kvl, 2048, 1024, vth, vtl);
    tgemm<128><<<dim3(8, 8, 64), 256, SM128>>>(
        qh, ql, 1024, (size_t)Sn * 1024, 64,
        kvh, kvl, 2048, (size_t)Sn * 2048, 64,
        nullptr, nullptr, sc, nullptr, nullptr, 1024, 16 * ZST, ZST, 64, 0, 0, 0);
    softmax_split<<<64 * Sn, 256>>>(sc, SCALE, 0, enc_mask, ph, pl);
    tgemm<64><<<dim3(1, 8, 64), 256, SM64>>>(
        ph, pl, 1024, 16 * ZST, ZST,
        vth, vtl, 1024, (size_t)16 * 64 * 1024, (size_t)64 * 1024,
        nullptr, nullptr, nullptr, ctxh, ctxl, 1024, (size_t)Sn * Dn, 64, 1024, 0, 0, 0);
    tgemm<128><<<dim3(8, M / 128, 1), 256, SM128>>>(
        ctxh, ctxl, 1024, 0, 0, wth + OW_CO, wtl + OW_CO, 1024, 0, 0,
        co_b, hb, hb, nullptr, nullptr, 1024, 0, 0, 1024, 0, 0, 0);

    // ==== FFN block ====
    ln_split<<<M, 256>>>(hb, ln3_w, ln3_b, lnh, lnl);
    tgemm<128><<<dim3(32, M / 128, 1), 256, SM128>>>(
        lnh, lnl, 1024, 0, 0, wth + OW_FI, wtl + OW_FI, 1024, 0, 0,
        fi_b, nullptr, nullptr, ffnh, ffnl, 4096, 0, 0, 1024, 1, 0, 0);
    tgemm<128><<<dim3(8, M / 128, 1), 256, SM128>>>(
        ffnh, ffnl, 4096, 0, 0, wth + OW_FO, wtl + OW_FO, 4096, 0, 0,
        fo_b, hb, out, nullptr, nullptr, 1024, 0, 0, 4096, 0, 0, 0);
}

// round 17
// speedup vs baseline: 1.3935x; 1.0434x over previous
#include <cuda_runtime.h>
#include <cuda_bf16.h>
#include <math.h>
#include <stdint.h>

// Problem constants
constexpr int Bn = 4, Sn = 1024, Tn = 1024, Dn = 1024, Fn = 4096;
constexpr int Mrows = Bn * Sn;           // 4096
constexpr float SCALE = 0.125f;          // 1/sqrt(64)

// ---------------- scratch (static device globals: allocation-free) -------------
__device__ __align__(256) float g_sc [(size_t)64 * Sn * Tn];   // 256 MB scores
__device__ __align__(256) float g_h  [Mrows * Dn];             // fp32 hidden

__device__ __align__(256) __nv_bfloat16 g_qkvh[Mrows * 3 * Dn];
__device__ __align__(256) __nv_bfloat16 g_qkvl[Mrows * 3 * Dn];
__device__ __align__(256) __nv_bfloat16 g_qh  [Mrows * Dn];
__device__ __align__(256) __nv_bfloat16 g_ql  [Mrows * Dn];
__device__ __align__(256) __nv_bfloat16 g_kvh [Mrows * 2 * Dn];
__device__ __align__(256) __nv_bfloat16 g_kvl [Mrows * 2 * Dn];
__device__ __align__(256) __nv_bfloat16 g_ph  [(size_t)64 * Sn * Tn];
__device__ __align__(256) __nv_bfloat16 g_pl  [(size_t)64 * Sn * Tn];
__device__ __align__(256) __nv_bfloat16 g_vth [64 * 64 * 1024];   // self-attn V^T
__device__ __align__(256) __nv_bfloat16 g_vtl [64 * 64 * 1024];
__device__ __align__(256) __nv_bfloat16 g_vth2[64 * 64 * 1024];   // cross-attn V^T
__device__ __align__(256) __nv_bfloat16 g_vtl2[64 * 64 * 1024];

__device__ __align__(256) __nv_bfloat16 g_lnh [Mrows * Dn];
__device__ __align__(256) __nv_bfloat16 g_lnl [Mrows * Dn];
__device__ __align__(256) __nv_bfloat16 g_ctxh[Mrows * Dn];
__device__ __align__(256) __nv_bfloat16 g_ctxl[Mrows * Dn];
__device__ __align__(256) __nv_bfloat16 g_ench[Mrows * Dn];
__device__ __align__(256) __nv_bfloat16 g_encl[Mrows * Dn];
__device__ __align__(256) __nv_bfloat16 g_ffnh[(size_t)Mrows * Fn];
__device__ __align__(256) __nv_bfloat16 g_ffnl[(size_t)Mrows * Fn];
__device__ __align__(256) __nv_bfloat16 g_wth[16 * 1024 * 1024];
__device__ __align__(256) __nv_bfloat16 g_wtl[16 * 1024 * 1024];
constexpr size_t OW_QKV = 0;
constexpr size_t OW_AO  = OW_QKV + 3u*1024*1024;
constexpr size_t OW_Q   = OW_AO  + 1u*1024*1024;
constexpr size_t OW_KV  = OW_Q   + 1u*1024*1024;
constexpr size_t OW_CO  = OW_KV  + 2u*1024*1024;
constexpr size_t OW_FI  = OW_CO  + 1u*1024*1024;
constexpr size_t OW_FO  = OW_FI  + 4u*1024*1024;

// ================= helpers ======================================================
__device__ __forceinline__ uint32_t s2u(const void* p) {
    uint32_t a;
    asm("{ .reg .u64 t; cvta.to.shared.u64 t, %1; cvt.u32.u64 %0, t; }" : "=r"(a) : "l"(p));
    return a;
}
__device__ __forceinline__ void ldsm4(uint32_t& r0, uint32_t& r1, uint32_t& r2, uint32_t& r3,
                                      uint32_t a) {
    asm volatile("ldmatrix.sync.aligned.m8n8.x4.shared.b16 {%0,%1,%2,%3}, [%4];"
        : "=r"(r0), "=r"(r1), "=r"(r2), "=r"(r3) : "r"(a));
}
__device__ __forceinline__ void mma16816(float* c, const uint32_t* a, uint32_t b0, uint32_t b1) {
    asm volatile(
        "mma.sync.aligned.m16n8k16.row.col.f32.bf16.bf16.f32 "
        "{%0,%1,%2,%3}, {%4,%5,%6,%7}, {%8,%9}, {%0,%1,%2,%3};"
        : "+f"(c[0]), "+f"(c[1]), "+f"(c[2]), "+f"(c[3])
        : "r"(a[0]), "r"(a[1]), "r"(a[2]), "r"(a[3]), "r"(b0), "r"(b1));
}
__device__ __forceinline__ void cpa16(uint32_t dst, const void* src) {
    asm volatile("cp.async.ca.shared.global [%0], [%1], 16;" :: "r"(dst), "l"(src));
}
__device__ __forceinline__ void split2(float x, __nv_bfloat16& h, __nv_bfloat16& l) {
    h = __float2bfloat16(x);
    l = __float2bfloat16(x - __bfloat162float(h));
}

// ================= tensor-core split-bf16 GEMM (mma.sync HMMA) ==================
// Batched: z = blockIdx.z, b=z>>4, h=z&15; operand offset = b*sXb + h*sXh.
// A split [*,K] (row stride lda), B split [N,K] (row stride ldb), both K-major.
// C = A@B^T (+bias)(+GELU)(+res); outputs fp32 (Cf) and/or split bf16 (Ch/Cl).
// trimask: skip tiles fully above the causal diagonal. kcausal: clamp K to the
// 128-row block's causal frontier AND reverse m-block order (long CTAs first,
// LPT scheduling for the imbalanced grid). __launch_bounds__(256,2): two CTAs
// per SM so one CTA's MMAs hide the other's cp.async wait + barrier latency.
template<int BN>
__global__ __launch_bounds__(256, 2)
void tgemm(const __nv_bfloat16* __restrict__ Ah_, const __nv_bfloat16* __restrict__ Al_,
           int lda, size_t sAb, size_t sAh,
           const __nv_bfloat16* __restrict__ Bh_, const __nv_bfloat16* __restrict__ Bl_,
           int ldb, size_t sBb, size_t sBh,
           const float* __restrict__ bias, const float* __restrict__ res,
           float* __restrict__ Cf, __nv_bfloat16* __restrict__ Ch, __nv_bfloat16* __restrict__ Cl,
           int ldc, size_t sCb, size_t sCh,
           int K, int gelu, int trimask, int kcausal)
{
    constexpr int STAGE = 16384 + BN * 128;      // bytes per pipeline stage
    constexpr int LP    = (128 + BN) * 8 / 256;  // 16B loads per thread per stage
    constexpr int NTC   = BN / 16;               // 8-col n-tiles per warp
    constexpr int NJ    = BN / 32;               // ldsm-b iterations

    extern __shared__ __align__(1024) char smraw[];
    const uint32_t sbase = s2u(smraw);
    const int tid = threadIdx.x, lane = tid & 31, wid = tid >> 5;
    const int z = blockIdx.z, zb = z >> 4, zh = z & 15;
    const int my = kcausal ? (gridDim.y - 1 - blockIdx.y) : blockIdx.y;
    const int m0 = my * 128, n0 = blockIdx.x * BN;
    const int wm = wid & 3, wn = wid >> 2;

    if (trimask && n0 > m0 + 127) return;        // fully-masked causal tile
    const int Ke = kcausal ? min(K, ((m0 >> 8) + 1) << 8) : K;

    const __nv_bfloat16* Ahp = Ah_ + zb * sAb + zh * sAh + (size_t)m0 * lda;
    const __nv_bfloat16* Alp = Al_ + zb * sAb + zh * sAh + (size_t)m0 * lda;
    const __nv_bfloat16* Bhp = Bh_ + zb * sBb + zh * sBh + (size_t)n0 * ldb;
    const __nv_bfloat16* Blp = Bl_ + zb * sBb + zh * sBh + (size_t)n0 * ldb;
    const size_t coff = zb * sCb + zh * sCh;

    float acc[2][NTC][4] = {};

    auto stage = [&](int st, int k0) {
        uint32_t dst0 = sbase + st * STAGE;
        #pragma unroll
        for (int p = 0; p < LP; p++) {
            int idx = tid + p * 256;
            int isB = idx >= 1024;
            int s = isB ? idx - 1024 : idx;
            int r = s >> 3, q = s & 7;
            const __nv_bfloat16* src = isB
                ? ((q < 4 ? Bhp : Blp) + (size_t)r * ldb + k0 + (q & 3) * 8)
                : ((q < 4 ? Ahp : Alp) + (size_t)r * lda + k0 + (q & 3) * 8);
            uint32_t dst = dst0 + isB * 16384 + r * 128 + ((q * 16) ^ ((r & 7) * 16));
            cpa16(dst, src);
        }
        asm volatile("cp.async.commit_group;" ::: "memory");
    };

    auto compute = [&](int st) {
        uint32_t sA = sbase + st * STAGE, sB = sA + 16384;
        #pragma unroll
        for (int ks = 0; ks < 2; ks++) {
            uint32_t ah[2][4], al[2][4];
            #pragma unroll
            for (int mt = 0; mt < 2; mt++) {
                int row = wm * 32 + mt * 16 + (lane & 15);
                int kb = ks * 32 + (lane >> 4) * 16;
                uint32_t rb = sA + row * 128;
                uint32_t xr = (row & 7) * 16;
                ldsm4(ah[mt][0], ah[mt][1], ah[mt][2], ah[mt][3], rb + (kb ^ xr));
                ldsm4(al[mt][0], al[mt][1], al[mt][2], al[mt][3], rb + ((kb + 64) ^ xr));
            }
            #pragma unroll
            for (int j = 0; j < NJ; j++) {
                int g = lane >> 3;
                int row = wn * (BN / 2) + (j * 2 + (g >> 1)) * 8 + (lane & 7);
                int kb = ks * 32 + (g & 1) * 16;
                uint32_t rb = sB + row * 128;
                uint32_t xr = (row & 7) * 16;
                uint32_t bh[4], bl[4];
                ldsm4(bh[0], bh[1], bh[2], bh[3], rb + (kb ^ xr));
                ldsm4(bl[0], bl[1], bl[2], bl[3], rb + ((kb + 64) ^ xr));
                #pragma unroll
                for (int mt = 0; mt < 2; mt++) {
                    #pragma unroll
                    for (int t = 0; t < 2; t++) {
                        float* c = acc[mt][j * 2 + t];
                        mma16816(c, ah[mt], bh[2 * t], bh[2 * t + 1]);
                        mma16816(c, ah[mt], bl[2 * t], bl[2 * t + 1]);
                        mma16816(c, al[mt], bh[2 * t], bh[2 * t + 1]);
                    }
                }
            }
        }
    };

    const int NC = Ke >> 5;
    stage(0, 0);
    for (int c = 0; c < NC; c++) {
        asm volatile("cp.async.wait_group 0;" ::: "memory");
        __syncthreads();
        if (c + 1 < NC) stage((c + 1) & 1, (c + 1) * 32);
        compute(c & 1);
    }

    // ---- epilogue ----
    const int r_in = lane >> 2, c_in = (lane & 3) * 2;
    #pragma unroll
    for (int mt = 0; mt < 2; mt++) {
        #pragma unroll
        for (int rr = 0; rr < 2; rr++) {
            int row = m0 + wm * 32 + mt * 16 + rr * 8 + r_in;
            #pragma unroll
            for (int nt = 0; nt < NTC; nt++) {
                int col = n0 + wn * (BN / 2) + nt * 8 + c_in;
                float v0 = acc[mt][nt][rr * 2 + 0];
                float v1 = acc[mt][nt][rr * 2 + 1];
                if (bias) { v0 += bias[col]; v1 += bias[col + 1]; }
                if (gelu) {
                    v0 = 0.5f * v0 * (1.0f + erff(v0 * 0.7071067811865476f));
                    v1 = 0.5f * v1 * (1.0f + erff(v1 * 0.7071067811865476f));
                }
                size_t off = coff + (size_t)row * ldc + col;
                if (res) {
                    float2 rr2 = *(const float2*)(res + off);
                    v0 += rr2.x; v1 += rr2.y;
                }
                if (Cf) *(float2*)(Cf + off) = make_float2(v0, v1);
                if (Ch) {
                    __nv_bfloat16 h0, l0, h1, l1;
                    split2(v0, h0, l0); split2(v1, h1, l1);
                    *(__nv_bfloat162*)(Ch + off) = __nv_bfloat162(h0, h1);
                    *(__nv_bfloat162*)(Cl + off) = __nv_bfloat162(l0, l1);
                }
            }
        }
    }
}

// ============== V transpose: vt[z][d][t] = v[(b*S+t)*ld + off + h*64 + d] =======
__global__ __launch_bounds__(256) void vtransT(
    const __nv_bfloat16* __restrict__ inh, const __nv_bfloat16* __restrict__ inl,
    int ld, int off, __nv_bfloat16* __restrict__ oth, __nv_bfloat16* __restrict__ otl)
{
    __shared__ __nv_bfloat16 th[32][33], tl[32][33];
    const int z = blockIdx.z, b = z >> 4, h = z & 15;
    const int t0 = blockIdx.x * 32, d0 = blockIdx.y * 32;
    const int tx = threadIdx.x & 31, ty = threadIdx.x >> 5;
    const __nv_bfloat16* sh = inh + (size_t)b * Sn * ld + off + h * 64 + d0;
    const __nv_bfloat16* sl = inl + (size_t)b * Sn * ld + off + h * 64 + d0;
    #pragma unroll
    for (int i = 0; i < 4; i++) {
        int t = t0 + ty + i * 8;
        th[ty + i * 8][tx] = sh[(size_t)t * ld + tx];
        tl[ty + i * 8][tx] = sl[(size_t)t * ld + tx];
    }
    __syncthreads();
    size_t obase = (size_t)z * 64 * 1024;
    #pragma unroll
    for (int i = 0; i < 4; i++) {
        int d = d0 + ty + i * 8;
        oth[obase + (size_t)d * 1024 + t0 + tx] = th[tx][ty + i * 8];
        otl[obase + (size_t)d * 1024 + t0 + tx] = tl[tx][ty + i * 8];
    }
}

// ============== weight transpose + split: W[K,N] -> Wh/Wl[N,K] bf16 =============
__global__ __launch_bounds__(256) void wsplitT(
    const float* __restrict__ W, __nv_bfloat16* __restrict__ oh,
    __nv_bfloat16* __restrict__ ol, int K, int N)
{
    __shared__ float t[32][33];
    int tx = threadIdx.x & 31, ty = threadIdx.x >> 5;
    int n0 = blockIdx.x * 32, k0 = blockIdx.y * 32;
    #pragma unroll
    for (int i = 0; i < 4; i++)
        t[ty + i * 8][tx] = W[(size_t)(k0 + ty + i * 8) * N + n0 + tx];
    __syncthreads();
    #pragma unroll
    for (int i = 0; i < 4; i++) {
        float v = t[tx][ty + i * 8];
        __nv_bfloat16 h, l;
        split2(v, h, l);
        size_t o = (size_t)(n0 + ty + i * 8) * K + k0 + tx;
        oh[o] = h; ol[o] = l;
    }
}

// ============== elementwise split (enc hidden states) ===========================
__global__ __launch_bounds__(256) void esplit(
    const float* __restrict__ x, __nv_bfloat16* __restrict__ oh,
    __nv_bfloat16* __restrict__ ol)
{
    int i = blockIdx.x * 256 + threadIdx.x;
    float4 v = ((const float4*)x)[i];
    __nv_bfloat16 h0, l0, h1, l1, h2, l2, h3, l3;
    split2(v.x, h0, l0); split2(v.y, h1, l1); split2(v.z, h2, l2); split2(v.w, h3, l3);
    ((__nv_bfloat162*)oh)[2 * i]     = __nv_bfloat162(h0, h1);
    ((__nv_bfloat162*)oh)[2 * i + 1] = __nv_bfloat162(h2, h3);
    ((__nv_bfloat162*)ol)[2 * i]     = __nv_bfloat162(l0, l1);
    ((__nv_bfloat162*)ol)[2 * i + 1] = __nv_bfloat162(l2, l3);
}

// ============== LayerNorm -> split bf16 =========================================
__global__ __launch_bounds__(256) void ln_split(
    const float* __restrict__ x, const float* __restrict__ w,
    const float* __restrict__ bb, __nv_bfloat16* __restrict__ yh,
    __nv_bfloat16* __restrict__ yl)
{
    const int row = blockIdx.x, tid = threadIdx.x;
    float4 v = ((const float4*)(x + (size_t)row * Dn))[tid];
    float s  = v.x + v.y + v.z + v.w;
    float sq = v.x * v.x + v.y * v.y + v.z * v.z + v.w * v.w;

    __shared__ float sm[18];
    #pragma unroll
    for (int off = 16; off > 0; off >>= 1) {
        s  += __shfl_xor_sync(~0u, s,  off);
        sq += __shfl_xor_sync(~0u, sq, off);
    }
    if ((tid & 31) == 0) { sm[tid >> 5] = s; sm[(tid >> 5) + 8] = sq; }
    __syncthreads();
    if (tid < 32) {
        float a  = (tid < 8) ? sm[tid]     : 0.f;
        float aq = (tid < 8) ? sm[tid + 8] : 0.f;
        #pragma unroll
        for (int off = 4; off > 0; off >>= 1) {
            a  += __shfl_xor_sync(~0u, a,  off);
            aq += __shfl_xor_sync(~0u, aq, off);
        }
        if (tid == 0) { sm[16] = a; sm[17] = aq; }
    }
    __syncthreads();
    const float mean = sm[16] * (1.0f / Dn);
    const float var  = sm[17] * (1.0f / Dn) - mean * mean;
    const float rstd = rsqrtf(var + 1e-12f);

    float4 w4 = ((const float4*)w)[tid];
    float4 b4 = ((const float4*)bb)[tid];
    float o0 = w4.x * (v.x - mean) * rstd + b4.x;
    float o1 = w4.y * (v.y - mean) * rstd + b4.y;
    float o2 = w4.z * (v.z - mean) * rstd + b4.z;
    float o3 = w4.w * (v.w - mean) * rstd + b4.w;
    __nv_bfloat16 h0, l0, h1, l1, h2, l2, h3, l3;
    split2(o0, h0, l0); split2(o1, h1, l1); split2(o2, h2, l2); split2(o3, h3, l3);
    size_t base = (size_t)row * Dn + tid * 4;
    ((__nv_bfloat162*)(yh + base))[0] = __nv_bfloat162(h0, h1);
    ((__nv_bfloat162*)(yh + base))[1] = __nv_bfloat162(h2, h3);
    ((__nv_bfloat162*)(yl + base))[0] = __nv_bfloat162(l0, l1);
    ((__nv_bfloat162*)(yl + base))[1] = __nv_bfloat162(l2, l3);
}

// ============== softmax: fp32 scores -> split-bf16 probs ========================
// causal: only process cols <= s (256-col chunks); masked cols get prob 0
// (matches reference: score -10000 -> exp underflows to exactly 0).
__global__ __launch_bounds__(256) void softmax_split(
    const float* __restrict__ sc, float scale, int causal,
    const float* __restrict__ addmask,
    __nv_bfloat16* __restrict__ ph, __nv_bfloat16* __restrict__ pl)
{
    const int row = blockIdx.x;
    const int s = row & (Sn - 1);
    const int b = row >> 14;
    const float* p = sc + (size_t)row * Tn;
    const int tid = threadIdx.x;

    const int ni = causal ? (s >> 8) + 1 : 4;   // 256-col chunks to process

    float vals[4];
    float mx = -1e30f;
    for (int i = 0; i < ni; i++) {
        int c = tid + i * 256;
        float v;
        if (causal && c > s) v = -10000.0f;
        else {
            v = p[c] * scale;
            if (!causal && addmask) v += addmask[(size_t)b * Tn + c];
        }
        vals[i] = v;
        mx = fmaxf(mx, v);
    }
    __shared__ float sm[18];
    #pragma unroll
    for (int off = 16; off > 0; off >>= 1) mx = fmaxf(mx, __shfl_xor_sync(~0u, mx, off));
    if ((tid & 31) == 0) sm[tid >> 5] = mx;
    __syncthreads();
    if (tid < 32) {
        float a = (tid < 8) ? sm[tid] : -1e30f;
        #pragma unroll
        for (int off = 4; off > 0; off >>= 1) a = fmaxf(a, __shfl_xor_sync(~0u, a, off));
        if (tid == 0) sm[16] = a;
    }
    __syncthreads();
    const float m = sm[16];

    float sum = 0.f;
    for (int i = 0; i < ni; i++) { vals[i] = expf(vals[i] - m); sum += vals[i]; }
    #pragma unroll
    for (int off = 16; off > 0; off >>= 1) sum += __shfl_xor_sync(~0u, sum, off);
    if ((tid & 31) == 0) sm[tid >> 5] = sum;
    __syncthreads();
    if (tid < 32) {
        float a = (tid < 8) ? sm[tid] : 0.f;
        #pragma unroll
        for (int off = 4; off > 0; off >>= 1) a += __shfl_xor_sync(~0u, a, off);
        if (tid == 0) sm[17] = a;
    }
    __syncthreads();
    const float inv = 1.0f / sm[17];
    for (int i = 0; i < ni; i++) {
        int c = tid + i * 256;
        __nv_bfloat16 hh, ll;
        split2(vals[i] * inv, hh, ll);
        ph[(size_t)row * Tn + c] = hh;
        pl[(size_t)row * Tn + c] = ll;
    }
}

// -------------------------------- launcher --------------------------------------
extern "C" void kernel_launch(void* const* d_in, const int* in_sizes, int n_in,
                              void* d_out, int out_size)
{
    const float* hid      = (const float*)d_in[0];
    const float* enc      = (const float*)d_in[1];
    const float* enc_mask = (const float*)d_in[2];
    const float *ln1_w = (const float*)d_in[4],  *ln1_b = (const float*)d_in[5];
    const float *qkv_w = (const float*)d_in[6],  *qkv_b = (const float*)d_in[7];
    const float *ao_w  = (const float*)d_in[8],  *ao_b  = (const float*)d_in[9];
    const float *ln2_w = (const float*)d_in[10], *ln2_b = (const float*)d_in[11];
    const float *q_w   = (const float*)d_in[12], *q_b   = (const float*)d_in[13];
    const float *kv_w  = (const float*)d_in[14], *kv_b  = (const float*)d_in[15];
    const float *co_w  = (const float*)d_in[16], *co_b  = (const float*)d_in[17];
    const float *ln3_w = (const float*)d_in[18], *ln3_b = (const float*)d_in[19];
    const float *fi_w  = (const float*)d_in[20], *fi_b  = (const float*)d_in[21];
    const float *fo_w  = (const float*)d_in[22], *fo_b  = (const float*)d_in[23];
    float* out = (float*)d_out;

    float *sc, *hb;
    __nv_bfloat16 *qkvh, *qkvl, *qh, *ql, *kvh, *kvl, *ph, *pl, *vth, *vtl, *vth2, *vtl2;
    __nv_bfloat16 *lnh, *lnl, *ctxh, *ctxl, *ench, *encl, *ffnh, *ffnl, *wth, *wtl;
    cudaGetSymbolAddress((void**)&sc,   g_sc);
    cudaGetSymbolAddress((void**)&hb,   g_h);
    cudaGetSymbolAddress((void**)&qkvh, g_qkvh);
    cudaGetSymbolAddress((void**)&qkvl, g_qkvl);
    cudaGetSymbolAddress((void**)&qh,   g_qh);
    cudaGetSymbolAddress((void**)&ql,   g_ql);
    cudaGetSymbolAddress((void**)&kvh,  g_kvh);
    cudaGetSymbolAddress((void**)&kvl,  g_kvl);
    cudaGetSymbolAddress((void**)&ph,   g_ph);
    cudaGetSymbolAddress((void**)&pl,   g_pl);
    cudaGetSymbolAddress((void**)&vth,  g_vth);
    cudaGetSymbolAddress((void**)&vtl,  g_vtl);
    cudaGetSymbolAddress((void**)&vth2, g_vth2);
    cudaGetSymbolAddress((void**)&vtl2, g_vtl2);
    cudaGetSymbolAddress((void**)&lnh,  g_lnh);
    cudaGetSymbolAddress((void**)&lnl,  g_lnl);
    cudaGetSymbolAddress((void**)&ctxh, g_ctxh);
    cudaGetSymbolAddress((void**)&ctxl, g_ctxl);
    cudaGetSymbolAddress((void**)&ench, g_ench);
    cudaGetSymbolAddress((void**)&encl, g_encl);
    cudaGetSymbolAddress((void**)&ffnh, g_ffnh);
    cudaGetSymbolAddress((void**)&ffnl, g_ffnl);
    cudaGetSymbolAddress((void**)&wth,  g_wth);
    cudaGetSymbolAddress((void**)&wtl,  g_wtl);

    static bool init_done = false;
    static cudaStream_t s2;
    static cudaEvent_t e_fork, e_w, e_kv;
    if (!init_done) {
        cudaFuncSetAttribute(tgemm<128>, cudaFuncAttributeMaxDynamicSharedMemorySize, 65536);
        cudaFuncSetAttribute(tgemm<64>,  cudaFuncAttributeMaxDynamicSharedMemorySize, 49152);
        cudaStreamCreateWithFlags(&s2, cudaStreamNonBlocking);
        cudaEventCreateWithFlags(&e_fork, cudaEventDisableTiming);
        cudaEventCreateWithFlags(&e_w,    cudaEventDisableTiming);
        cudaEventCreateWithFlags(&e_kv,   cudaEventDisableTiming);
        init_done = true;
    }
    const int SM128 = 65536, SM64 = 49152;
    const int M = Mrows;  // 4096
    const size_t ZST = (size_t)Sn * Tn;

    // ---- QKV weight prep (critical path) on main; everything else forked to s2.
    // s2 also runs the full cross-attn KV pipeline (projection + V transpose),
    // which depends only on inputs — it overlaps the entire self-attn block.
    wsplitT<<<dim3(3072 / 32, 1024 / 32), 256>>>(qkv_w, wth + OW_QKV, wtl + OW_QKV, 1024, 3072);
    cudaEventRecord(e_fork, 0);
    cudaStreamWaitEvent(s2, e_fork, 0);
    wsplitT<<<dim3(1024 / 32, 1024 / 32), 256, 0, s2>>>(ao_w,  wth + OW_AO,  wtl + OW_AO,  1024, 1024);
    wsplitT<<<dim3(1024 / 32, 1024 / 32), 256, 0, s2>>>(q_w,   wth + OW_Q,   wtl + OW_Q,   1024, 1024);
    wsplitT<<<dim3(1024 / 32, 1024 / 32), 256, 0, s2>>>(co_w,  wth + OW_CO,  wtl + OW_CO,  1024, 1024);
    wsplitT<<<dim3(4096 / 32, 1024 / 32), 256, 0, s2>>>(fi_w,  wth + OW_FI,  wtl + OW_FI,  1024, 4096);
    wsplitT<<<dim3(1024 / 32, 4096 / 32), 256, 0, s2>>>(fo_w,  wth + OW_FO,  wtl + OW_FO,  4096, 1024);
    cudaEventRecord(e_w, s2);
    wsplitT<<<dim3(2048 / 32, 1024 / 32), 256, 0, s2>>>(kv_w,  wth + OW_KV,  wtl + OW_KV,  1024, 2048);
    esplit<<<(M * Dn / 4) / 256, 256, 0, s2>>>(enc, ench, encl);
    tgemm<128><<<dim3(16, M / 128, 1), 256, SM128, s2>>>(            // cross-attn KV proj
        ench, encl, 1024, 0, 0, wth + OW_KV, wtl + OW_KV, 1024, 0, 0,
        kv_b, nullptr, nullptr, kvh, kvl, 2048, 0, 0, 1024, 0, 0, 0);
    vtransT<<<dim3(32, 2, 64), 256, 0, s2>>>(kvh, kvl, 2048, 1024, vth2, vtl2);
    cudaEventRecord(e_kv, s2);

    // ==== self-attention block (overlaps with s2 work) ====
    ln_split<<<M, 256>>>(hid, ln1_w, ln1_b, lnh, lnl);
    tgemm<128><<<dim3(24, M / 128, 1), 256, SM128>>>(
        lnh, lnl, 1024, 0, 0, wth + OW_QKV, wtl + OW_QKV, 1024, 0, 0,
        qkv_b, nullptr, nullptr, qkvh, qkvl, 3072, 0, 0, 1024, 0, 0, 0);
    vtransT<<<dim3(32, 2, 64), 256>>>(qkvh, qkvl, 3072, 2048, vth, vtl);
    tgemm<128><<<dim3(8, 8, 64), 256, SM128>>>(                       // scores = Q.K^T
        qkvh, qkvl, 3072, (size_t)Sn * 3072, 64,
        qkvh + 1024, qkvl + 1024, 3072, (size_t)Sn * 3072, 64,
        nullptr, nullptr, sc, nullptr, nullptr, 1024, 16 * ZST, ZST, 64, 0, 1, 0);
    softmax_split<<<64 * Sn, 256>>>(sc, SCALE, 1, nullptr, ph, pl);
    tgemm<64><<<dim3(1, 8, 64), 256, SM64>>>(                          // ctx = P.V
        ph, pl, 1024, 16 * ZST, ZST,
        vth, vtl, 1024, (size_t)16 * 64 * 1024, (size_t)64 * 1024,
        nullptr, nullptr, nullptr, ctxh, ctxl, 1024, (size_t)Sn * Dn, 64, 1024, 0, 0, 1);

    cudaStreamWaitEvent(0, e_w, 0);      // AO/Q/CO/FI/FO weights ready
    tgemm<128><<<dim3(8, M / 128, 1), 256, SM128>>>(
        ctxh, ctxl, 1024, 0, 0, wth + OW_AO, wtl + OW_AO, 1024, 0, 0,
        ao_b, hid, hb, nullptr, nullptr, 1024, 0, 0, 1024, 0, 0, 0);

    // ==== cross-attention block ====
    ln_split<<<M, 256>>>(hb, ln2_w, ln2_b, lnh, lnl);
    tgemm<128><<<dim3(8, M / 128, 1), 256, SM128>>>(
        lnh, lnl, 1024, 0, 0, wth + OW_Q, wtl + OW_Q, 1024, 0, 0,
        q_b, nullptr, nullptr, qh, ql, 1024, 0, 0, 1024, 0, 0, 0);
    cudaStreamWaitEvent(0, e_kv, 0);     // KV projection + V^T ready (from s2)
    tgemm<128><<<dim3(8, 8, 64), 256, SM128>>>(
        qh, ql, 1024, (size_t)Sn * 1024, 64,
        kvh, kvl, 2048, (size_t)Sn * 2048, 64,
        nullptr, nullptr, sc, nullptr, nullptr, 1024, 16 * ZST, ZST, 64, 0, 0, 0);
    softmax_split<<<64 * Sn, 256>>>(sc, SCALE, 0, enc_mask, ph, pl);
    tgemm<64><<<dim3(1, 8, 64), 256, SM64>>>(
        ph, pl, 1024, 16 * ZST, ZST,
        vth2, vtl2, 1024, (size_t)16 * 64 * 1024, (size_t)64 * 1024,
        nullptr, nullptr, nullptr, ctxh, ctxl, 1024, (size_t)Sn * Dn, 64, 1024, 0, 0, 0);
    tgemm<128><<<dim3(8, M / 128, 1), 256, SM128>>>(
        ctxh, ctxl, 1024, 0, 0, wth + OW_CO, wtl + OW_CO, 1024, 0, 0,
        co_b, hb, hb, nullptr, nullptr, 1024, 0, 0, 1024, 0, 0, 0);

    // ==== FFN block ====
    ln_split<<<M, 256>>>(hb, ln3_w, ln3_b, lnh, lnl);
    tgemm<128><<<dim3(32, M / 128, 1), 256, SM128>>>(
        lnh, lnl, 1024, 0, 0, wth + OW_FI, wtl + OW_FI, 1024, 0, 0,
        fi_b, nullptr, nullptr, ffnh, ffnl, 4096, 0, 0, 1024, 1, 0, 0);
    tgemm<128><<<dim3(8, M / 128, 1), 256, SM128>>>(
        ffnh, ffnl, 4096, 0, 0, wth + OW_FO, wtl + OW_FO, 4096, 0, 0,
        fo_b, hb, out, nullptr, nullptr, 1024, 0, 0, 4096, 0, 0, 0);
}